// round 3
// baseline (speedup 1.0000x reference)
#include <cuda_runtime.h>
#include <cuda_bf16.h>
#include <math.h>

#define N_ENT   64368
#define DIM     128
#define BATCH   512
#define SEQ     50
#define NT      503      // ceil(64368/128) column tiles
#define NTP     512      // padded partial stride
#define BM      128
#define BN      128
#define KC      32       // k-chunk
#define CPAD    36       // smem k-stride (bank-conflict-free for frag loads)

// ---------------- scratch (device globals; no allocations allowed) ----------
__device__ float g_r1[DIM];
__device__ float g_r2[DIM];
__device__ float g_c;
__device__ __align__(16) float g_u[BATCH * DIM];
__device__ float g_pm[BATCH * NTP];
__device__ float g_ps[BATCH * NTP];
__device__ float g_lp[BATCH];

// ---------------- helpers ----------------------------------------------------
__device__ __forceinline__ unsigned f2tf(float x) {
    unsigned r;
    asm("cvt.rna.tf32.f32 %0, %1;" : "=r"(r) : "f"(x));
    return r;
}

__device__ __forceinline__ void mma_tf32(float* d, const unsigned* a, unsigned b0, unsigned b1) {
    asm volatile(
        "mma.sync.aligned.m16n8k8.row.col.f32.tf32.tf32.f32 "
        "{%0,%1,%2,%3}, {%4,%5,%6,%7}, {%8,%9}, {%0,%1,%2,%3};\n"
        : "+f"(d[0]), "+f"(d[1]), "+f"(d[2]), "+f"(d[3])
        : "r"(a[0]), "r"(a[1]), "r"(a[2]), "r"(a[3]), "r"(b0), "r"(b1));
}

// ---------------- kernel 1: r1 = W1^T q, r2 = W2^T q, c = soft_bias * sum(q) -
__global__ void prep_kernel(const float* __restrict__ W1, const float* __restrict__ W2,
                            const float* __restrict__ q,  const float* __restrict__ soft_bias) {
    int d = threadIdx.x;               // 128 threads
    __shared__ float sq[DIM];
    __shared__ float red[DIM];
    sq[d] = q[d];
    __syncthreads();
    float r1 = 0.f, r2 = 0.f;
    #pragma unroll 8
    for (int e = 0; e < DIM; e++) {
        float qe = sq[e];
        r1 += qe * W1[e * DIM + d];
        r2 += qe * W2[e * DIM + d];
    }
    g_r1[d] = r1;
    g_r2[d] = r2;
    red[d] = sq[d];
    __syncthreads();
    for (int s = 64; s > 0; s >>= 1) {
        if (d < s) red[d] += red[d + s];
        __syncthreads();
    }
    if (d == 0) g_c = soft_bias[0] * red[0];
}

// ---------------- kernel 2: u_emb[b,:] = sum_l att[b,l] * v[b,l,:] -----------
__global__ void uemb_kernel(const float* __restrict__ emb,
                            const int* __restrict__ seeds) {
    int b = blockIdx.x;
    int d = threadIdx.x;               // 128 threads, thread = dim
    int warp = d >> 5, lane = d & 31;

    __shared__ float v[SEQ][DIM];
    __shared__ float att[SEQ];
    __shared__ float sr1[DIM], sr2[DIM];
    __shared__ float dn;

    sr1[d] = g_r1[d];
    sr2[d] = g_r2[d];

    // positional-encoding frequency for this dim
    float w = expf(-(float)(d & ~1) * (logf(10000.0f) / (float)DIM));
    bool odd = (d & 1);

    // gather v = emb[seed] + pe
    for (int l = 0; l < SEQ; l++) {
        int idx = seeds[b * SEQ + l];
        float arg = (float)l * w;
        float pe = (odd ? cosf(arg) : sinf(arg)) * 0.001f;
        v[l][d] = emb[(size_t)idx * DIM + d] + pe;
    }
    __syncthreads();

    // att_raw[l] = r1 . v[l]   (one warp per l, strided)
    for (int l = warp; l < SEQ; l += 4) {
        float p = sr1[lane]      * v[l][lane]
                + sr1[lane + 32] * v[l][lane + 32]
                + sr1[lane + 64] * v[l][lane + 64]
                + sr1[lane + 96] * v[l][lane + 96];
        #pragma unroll
        for (int o = 16; o; o >>= 1) p += __shfl_xor_sync(0xffffffffu, p, o);
        if (lane == 0) att[l] = p;
    }
    // dn = r2 . v[49] + c
    if (warp == 0) {
        float p = sr2[lane]      * v[SEQ - 1][lane]
                + sr2[lane + 32] * v[SEQ - 1][lane + 32]
                + sr2[lane + 64] * v[SEQ - 1][lane + 64]
                + sr2[lane + 96] * v[SEQ - 1][lane + 96];
        #pragma unroll
        for (int o = 16; o; o >>= 1) p += __shfl_xor_sync(0xffffffffu, p, o);
        if (lane == 0) dn = p + g_c;
    }
    __syncthreads();
    if (d < SEQ) att[d] += dn;
    __syncthreads();

    float acc = 0.f;
    #pragma unroll 10
    for (int l = 0; l < SEQ; l++) acc += att[l] * v[l][d];
    g_u[b * DIM + d] = acc;
}

// ---------------- kernel 3: scores GEMM (tf32 mma) + fused streaming LSE -----
__global__ void __launch_bounds__(256, 2)
gemm_kernel(const float* __restrict__ emb, const float* __restrict__ out_bias,
            float* __restrict__ out) {
    __shared__ unsigned sA[BM * CPAD];
    __shared__ unsigned sB[BN * CPAD];
    __shared__ float    sBias[BN];
    __shared__ float    sRm[BM * 2];
    __shared__ float    sRs[BM * 2];

    const int tid  = threadIdx.x;
    const int warp = tid >> 5, lane = tid & 31;
    const int wm   = warp & 3;          // warp m index (4)
    const int wn   = warp >> 2;         // warp n index (2)
    const int m0   = blockIdx.x * BM;
    const int n0   = blockIdx.y * BN;

    if (tid < BN) {
        int g = n0 + tid;
        sBias[tid] = (g < N_ENT) ? out_bias[g] : 0.f;
    }

    float acc[2][8][4];
    #pragma unroll
    for (int i = 0; i < 2; i++)
        #pragma unroll
        for (int j = 0; j < 8; j++)
            #pragma unroll
            for (int k = 0; k < 4; k++) acc[i][j][k] = 0.f;

    for (int kc = 0; kc < DIM; kc += KC) {
        // load A chunk (u_emb): 128 x 32 floats
        #pragma unroll
        for (int i = 0; i < 4; i++) {
            int idx = tid + i * 256;
            int r = idx >> 3, kq = (idx & 7) << 2;
            float4 va = *(const float4*)&g_u[(m0 + r) * DIM + kc + kq];
            unsigned* dst = &sA[r * CPAD + kq];
            dst[0] = f2tf(va.x); dst[1] = f2tf(va.y);
            dst[2] = f2tf(va.z); dst[3] = f2tf(va.w);
        }
        // load B chunk (entity_emb): 128 x 32 floats, row-predicated
        #pragma unroll
        for (int i = 0; i < 4; i++) {
            int idx = tid + i * 256;
            int r = idx >> 3, kq = (idx & 7) << 2;
            int g = n0 + r;
            float4 vb = make_float4(0.f, 0.f, 0.f, 0.f);
            if (g < N_ENT) vb = *(const float4*)&emb[(size_t)g * DIM + kc + kq];
            unsigned* dst = &sB[r * CPAD + kq];
            dst[0] = f2tf(vb.x); dst[1] = f2tf(vb.y);
            dst[2] = f2tf(vb.z); dst[3] = f2tf(vb.w);
        }
        __syncthreads();

        #pragma unroll
        for (int ks = 0; ks < 4; ks++) {
            const int k0 = ks * 8;
            unsigned a[2][4];
            const int ar = wm * 32 + (lane >> 2);
            const int ac = k0 + (lane & 3);
            #pragma unroll
            for (int mf = 0; mf < 2; mf++) {
                a[mf][0] = sA[(ar + mf * 16)     * CPAD + ac];
                a[mf][1] = sA[(ar + mf * 16 + 8) * CPAD + ac];
                a[mf][2] = sA[(ar + mf * 16)     * CPAD + ac + 4];
                a[mf][3] = sA[(ar + mf * 16 + 8) * CPAD + ac + 4];
            }
            #pragma unroll
            for (int nf = 0; nf < 8; nf++) {
                int br = wn * 64 + nf * 8 + (lane >> 2);
                unsigned b0 = sB[br * CPAD + k0 + (lane & 3)];
                unsigned b1 = sB[br * CPAD + k0 + (lane & 3) + 4];
                mma_tf32(acc[0][nf], a[0], b0, b1);
                mma_tf32(acc[1][nf], a[1], b0, b1);
            }
        }
        __syncthreads();
    }

    // ---- epilogue: add bias, store scores, streaming (max,sumexp) partials --
    const float NEG = -1e30f;
    #pragma unroll
    for (int mf = 0; mf < 2; mf++) {
        #pragma unroll
        for (int h = 0; h < 2; h++) {
            const int rl = wm * 32 + mf * 16 + h * 8 + (lane >> 2);
            const long grow = (long)(m0 + rl) * N_ENT;
            float mx = NEG;
            #pragma unroll
            for (int nf = 0; nf < 8; nf++) {
                int c = wn * 64 + nf * 8 + ((lane & 3) << 1);
                int g = n0 + c;
                float v0 = acc[mf][nf][2 * h]     + sBias[c];
                float v1 = acc[mf][nf][2 * h + 1] + sBias[c + 1];
                if (g + 1 < N_ENT) {
                    *(float2*)&out[grow + g] = make_float2(v0, v1);
                } else if (g < N_ENT) {
                    out[grow + g] = v0;
                    v1 = NEG;
                } else {
                    v0 = NEG; v1 = NEG;
                }
                acc[mf][nf][2 * h]     = v0;
                acc[mf][nf][2 * h + 1] = v1;
                mx = fmaxf(mx, fmaxf(v0, v1));
            }
            float s = 0.f;
            #pragma unroll
            for (int nf = 0; nf < 8; nf++)
                s += __expf(acc[mf][nf][2 * h] - mx) + __expf(acc[mf][nf][2 * h + 1] - mx);
            // combine across the 4 lanes sharing this row
            #pragma unroll
            for (int off = 1; off <= 2; off <<= 1) {
                float om = __shfl_xor_sync(0xffffffffu, mx, off);
                float os = __shfl_xor_sync(0xffffffffu, s,  off);
                float nm = fmaxf(mx, om);
                s = s * __expf(mx - nm) + os * __expf(om - nm);
                mx = nm;
            }
            if ((lane & 3) == 0) {
                sRm[rl * 2 + wn] = mx;
                sRs[rl * 2 + wn] = s;
            }
        }
    }
    __syncthreads();
    if (tid < BM) {
        float ma = sRm[tid * 2], mb = sRm[tid * 2 + 1];
        float sa = sRs[tid * 2], sb = sRs[tid * 2 + 1];
        float nm = fmaxf(ma, mb);
        float s  = sa * __expf(ma - nm) + sb * __expf(mb - nm);
        g_pm[(m0 + tid) * NTP + blockIdx.y] = nm;
        g_ps[(m0 + tid) * NTP + blockIdx.y] = s;
    }
}

// ---------------- kernel 4: per-row logsumexp + picked -----------------------
__global__ void lse_kernel(const float* __restrict__ out,
                           const int* __restrict__ labels) {
    int b = blockIdx.x;
    int tid = threadIdx.x;             // 128
    float mx = -1e30f, s = 0.f;
    for (int t = tid; t < NT; t += 128) {
        float m = g_pm[b * NTP + t];
        float p = g_ps[b * NTP + t];
        float nm = fmaxf(mx, m);
        s = s * __expf(mx - nm) + p * __expf(m - nm);
        mx = nm;
    }
    __shared__ float sm[128], ss[128];
    sm[tid] = mx; ss[tid] = s;
    __syncthreads();
    for (int o = 64; o; o >>= 1) {
        if (tid < o) {
            float m2 = sm[tid + o], s2 = ss[tid + o];
            float nm = fmaxf(sm[tid], m2);
            ss[tid] = ss[tid] * __expf(sm[tid] - nm) + s2 * __expf(m2 - nm);
            sm[tid] = nm;
        }
        __syncthreads();
    }
    if (tid == 0) {
        float logz = sm[0] + logf(ss[0]);
        int lab = labels[b];
        float picked = out[(long)b * N_ENT + lab];
        g_lp[b] = logz - picked;
    }
}

// ---------------- kernel 5: mean loss -> tail of d_out ------------------------
__global__ void loss_kernel(float* __restrict__ out, int out_size) {
    int tid = threadIdx.x;             // 512
    __shared__ float red[BATCH];
    red[tid] = g_lp[tid];
    __syncthreads();
    for (int o = 256; o; o >>= 1) {
        if (tid < o) red[tid] += red[tid + o];
        __syncthreads();
    }
    __shared__ float loss_s;
    if (tid == 0) loss_s = red[0] / (float)BATCH;
    __syncthreads();
    const long base = (long)BATCH * N_ENT;
    for (long i = base + tid; i < (long)out_size; i += 512)
        out[i] = loss_s;
}

// ---------------- launch ------------------------------------------------------
extern "C" void kernel_launch(void* const* d_in, const int* in_sizes, int n_in,
                              void* d_out, int out_size) {
    const float* entity_emb = (const float*)d_in[0];
    const float* W1         = (const float*)d_in[1];
    const float* W2         = (const float*)d_in[2];
    const float* q          = (const float*)d_in[3];
    const float* soft_bias  = (const float*)d_in[4];
    const float* out_bias   = (const float*)d_in[5];
    const int*   seed_sets  = (const int*)d_in[6];   // jax default: int64 request -> int32
    const int*   labels     = (const int*)d_in[7];
    float* out = (float*)d_out;

    prep_kernel<<<1, 128>>>(W1, W2, q, soft_bias);
    uemb_kernel<<<BATCH, 128>>>(entity_emb, seed_sets);
    gemm_kernel<<<dim3(BATCH / BM, NT), 256>>>(entity_emb, out_bias, out);
    lse_kernel<<<BATCH, 128>>>(out, labels);
    loss_kernel<<<1, BATCH>>>(out, out_size);
}

// round 4
// speedup vs baseline: 1.0876x; 1.0876x over previous
#include <cuda_runtime.h>
#include <cuda_bf16.h>
#include <math.h>

#define N_ENT   64368
#define DIM     128
#define BATCH   512
#define SEQ     50
#define NT      503      // ceil(64368/128) column tiles
#define NTP     512      // padded partial stride
#define BM      128
#define BN      128
#define KC      32       // k-chunk
#define NCHUNK  4        // DIM / KC
#define CPAD    36       // smem k-stride in words (bank-conflict-free frag loads)
#define SW      (BM * CPAD)   // words per tile buffer (4608)

// ---------------- scratch (device globals; no allocations allowed) ----------
__device__ float g_r1[DIM];
__device__ float g_r2[DIM];
__device__ float g_c;
__device__ __align__(16) float g_u[BATCH * DIM];
__device__ __align__(16) float2 g_pms[BATCH * NTP];
__device__ float g_lp[BATCH];

// ---------------- helpers ----------------------------------------------------
__device__ __forceinline__ unsigned f2tf(float x) {
    unsigned r;
    asm("cvt.rna.tf32.f32 %0, %1;" : "=r"(r) : "f"(x));
    return r;
}

__device__ __forceinline__ void mma_tf32(float* d, const unsigned* a, unsigned b0, unsigned b1) {
    asm volatile(
        "mma.sync.aligned.m16n8k8.row.col.f32.tf32.tf32.f32 "
        "{%0,%1,%2,%3}, {%4,%5,%6,%7}, {%8,%9}, {%0,%1,%2,%3};\n"
        : "+f"(d[0]), "+f"(d[1]), "+f"(d[2]), "+f"(d[3])
        : "r"(a[0]), "r"(a[1]), "r"(a[2]), "r"(a[3]), "r"(b0), "r"(b1));
}

__device__ __forceinline__ void cp_async16(unsigned dst_smem, const void* src, int sz) {
    asm volatile("cp.async.cg.shared.global [%0], [%1], 16, %2;\n"
                 :: "r"(dst_smem), "l"(src), "r"(sz));
}
__device__ __forceinline__ void cp_commit() {
    asm volatile("cp.async.commit_group;\n");
}
template <int N>
__device__ __forceinline__ void cp_wait() {
    asm volatile("cp.async.wait_group %0;\n" :: "n"(N));
}

// ---------------- kernel 1: r1 = W1^T q, r2 = W2^T q, c = soft_bias * sum(q) -
__global__ void prep_kernel(const float* __restrict__ W1, const float* __restrict__ W2,
                            const float* __restrict__ q,  const float* __restrict__ soft_bias) {
    int d = threadIdx.x;               // 128 threads
    __shared__ float sq[DIM];
    __shared__ float red[DIM];
    sq[d] = q[d];
    __syncthreads();
    float r1 = 0.f, r2 = 0.f;
    #pragma unroll 8
    for (int e = 0; e < DIM; e++) {
        float qe = sq[e];
        r1 += qe * W1[e * DIM + d];
        r2 += qe * W2[e * DIM + d];
    }
    g_r1[d] = r1;
    g_r2[d] = r2;
    red[d] = sq[d];
    __syncthreads();
    for (int s = 64; s > 0; s >>= 1) {
        if (d < s) red[d] += red[d + s];
        __syncthreads();
    }
    if (d == 0) g_c = soft_bias[0] * red[0];
}

// ---------------- kernel 2: u_emb[b,:] = sum_l att[b,l] * v[b,l,:] -----------
// Output is pre-rounded to tf32 so the GEMM A operand is exact.
__global__ void uemb_kernel(const float* __restrict__ emb,
                            const int* __restrict__ seeds) {
    int b = blockIdx.x;
    int d = threadIdx.x;               // 128 threads, thread = dim
    int warp = d >> 5, lane = d & 31;

    __shared__ float v[SEQ][DIM];
    __shared__ float att[SEQ];
    __shared__ float sr1[DIM], sr2[DIM];
    __shared__ float dn;

    sr1[d] = g_r1[d];
    sr2[d] = g_r2[d];

    float w = expf(-(float)(d & ~1) * (logf(10000.0f) / (float)DIM));
    bool odd = (d & 1);

    for (int l = 0; l < SEQ; l++) {
        int idx = seeds[b * SEQ + l];
        float arg = (float)l * w;
        float pe = (odd ? cosf(arg) : sinf(arg)) * 0.001f;
        v[l][d] = emb[(size_t)idx * DIM + d] + pe;
    }
    __syncthreads();

    for (int l = warp; l < SEQ; l += 4) {
        float p = sr1[lane]      * v[l][lane]
                + sr1[lane + 32] * v[l][lane + 32]
                + sr1[lane + 64] * v[l][lane + 64]
                + sr1[lane + 96] * v[l][lane + 96];
        #pragma unroll
        for (int o = 16; o; o >>= 1) p += __shfl_xor_sync(0xffffffffu, p, o);
        if (lane == 0) att[l] = p;
    }
    if (warp == 0) {
        float p = sr2[lane]      * v[SEQ - 1][lane]
                + sr2[lane + 32] * v[SEQ - 1][lane + 32]
                + sr2[lane + 64] * v[SEQ - 1][lane + 64]
                + sr2[lane + 96] * v[SEQ - 1][lane + 96];
        #pragma unroll
        for (int o = 16; o; o >>= 1) p += __shfl_xor_sync(0xffffffffu, p, o);
        if (lane == 0) dn = p + g_c;
    }
    __syncthreads();
    if (d < SEQ) att[d] += dn;
    __syncthreads();

    float acc = 0.f;
    #pragma unroll 10
    for (int l = 0; l < SEQ; l++) acc += att[l] * v[l][d];
    g_u[b * DIM + d] = __uint_as_float(f2tf(acc));   // tf32-exact A operand
}

// ---------------- kernel 3: scores GEMM (tf32 mma) + fused streaming LSE -----
// 2-stage cp.async pipeline, raw-f32 operands (hw truncates to tf32).
extern __shared__ float dynsmem[];   // [2 stages][A:SW | B:SW] words

__global__ void __launch_bounds__(256, 2)
gemm_kernel(const float* __restrict__ emb, const float* __restrict__ out_bias,
            float* __restrict__ out) {
    __shared__ float sBias[BN];
    __shared__ float sRm[BM * 2];
    __shared__ float sRs[BM * 2];

    const int tid  = threadIdx.x;
    const int warp = tid >> 5, lane = tid & 31;
    const int wm   = warp & 3;          // warp m index (4)
    const int wn   = warp >> 2;         // warp n index (2)
    const int m0   = blockIdx.x * BM;
    const int n0   = blockIdx.y * BN;

    const unsigned smem_base = (unsigned)__cvta_generic_to_shared(dynsmem);

    if (tid < BN) {
        int g = n0 + tid;
        sBias[tid] = (g < N_ENT) ? out_bias[g] : 0.f;
    }

    // per-thread load geometry: 16B per cp.async, 8 segments per 128B row
    const int lr  = tid >> 3;          // row 0..31 (stride 32 over i)
    const int seg = tid & 7;           // 16B segment within 32-float row

    // issue one chunk's loads (A + B) into a stage
    auto load_chunk = [&](int kc, int stage) {
        const unsigned aBase = smem_base + (unsigned)(stage * 2 * SW) * 4u;
        const unsigned bBase = aBase + (unsigned)SW * 4u;
        #pragma unroll
        for (int i = 0; i < 4; i++) {
            int r = lr + i * 32;
            unsigned dst = aBase + (unsigned)(r * CPAD + seg * 4) * 4u;
            cp_async16(dst, &g_u[(m0 + r) * DIM + kc + seg * 4], 16);
        }
        #pragma unroll
        for (int i = 0; i < 4; i++) {
            int r = lr + i * 32;
            int g = n0 + r;
            int gc = g < N_ENT ? g : 0;
            unsigned dst = bBase + (unsigned)(r * CPAD + seg * 4) * 4u;
            cp_async16(dst, &emb[(size_t)gc * DIM + kc + seg * 4],
                       g < N_ENT ? 16 : 0);
        }
    };

    float acc[2][8][4];
    #pragma unroll
    for (int i = 0; i < 2; i++)
        #pragma unroll
        for (int j = 0; j < 8; j++)
            #pragma unroll
            for (int k = 0; k < 4; k++) acc[i][j][k] = 0.f;

    load_chunk(0, 0); cp_commit();
    load_chunk(KC, 1); cp_commit();

    #pragma unroll
    for (int c = 0; c < NCHUNK; c++) {
        if (c < NCHUNK - 1) cp_wait<1>(); else cp_wait<0>();
        __syncthreads();

        const unsigned* sA = (const unsigned*)(dynsmem + (c & 1) * 2 * SW);
        const unsigned* sB = sA + SW;

        #pragma unroll
        for (int ks = 0; ks < 4; ks++) {
            const int k0 = ks * 8;
            unsigned a[2][4];
            const int ar = wm * 32 + (lane >> 2);
            const int ac = k0 + (lane & 3);
            #pragma unroll
            for (int mf = 0; mf < 2; mf++) {
                a[mf][0] = sA[(ar + mf * 16)     * CPAD + ac];
                a[mf][1] = sA[(ar + mf * 16 + 8) * CPAD + ac];
                a[mf][2] = sA[(ar + mf * 16)     * CPAD + ac + 4];
                a[mf][3] = sA[(ar + mf * 16 + 8) * CPAD + ac + 4];
            }
            #pragma unroll
            for (int nf = 0; nf < 8; nf++) {
                int br = wn * 64 + nf * 8 + (lane >> 2);
                unsigned b0 = sB[br * CPAD + k0 + (lane & 3)];
                unsigned b1 = sB[br * CPAD + k0 + (lane & 3) + 4];
                mma_tf32(acc[0][nf], a[0], b0, b1);
                mma_tf32(acc[1][nf], a[1], b0, b1);
            }
        }

        if (c < NCHUNK - 2) {
            __syncthreads();                       // stage (c&1) fully consumed
            load_chunk((c + 2) * KC, c & 1);
            cp_commit();
        }
    }

    // ---- epilogue: add bias, store scores, streaming (max,sumexp) partials --
    const float NEG = -1e30f;
    #pragma unroll
    for (int mf = 0; mf < 2; mf++) {
        #pragma unroll
        for (int h = 0; h < 2; h++) {
            const int rl = wm * 32 + mf * 16 + h * 8 + (lane >> 2);
            const long grow = (long)(m0 + rl) * N_ENT;
            float mx = NEG;
            #pragma unroll
            for (int nf = 0; nf < 8; nf++) {
                int c = wn * 64 + nf * 8 + ((lane & 3) << 1);
                int g = n0 + c;
                float v0 = acc[mf][nf][2 * h]     + sBias[c];
                float v1 = acc[mf][nf][2 * h + 1] + sBias[c + 1];
                if (g + 1 < N_ENT) {
                    *(float2*)&out[grow + g] = make_float2(v0, v1);
                } else if (g < N_ENT) {
                    out[grow + g] = v0;
                    v1 = NEG;
                } else {
                    v0 = NEG; v1 = NEG;
                }
                acc[mf][nf][2 * h]     = v0;
                acc[mf][nf][2 * h + 1] = v1;
                mx = fmaxf(mx, fmaxf(v0, v1));
            }
            float s = 0.f;
            #pragma unroll
            for (int nf = 0; nf < 8; nf++)
                s += __expf(acc[mf][nf][2 * h] - mx) + __expf(acc[mf][nf][2 * h + 1] - mx);
            #pragma unroll
            for (int off = 1; off <= 2; off <<= 1) {
                float om = __shfl_xor_sync(0xffffffffu, mx, off);
                float os = __shfl_xor_sync(0xffffffffu, s,  off);
                float nm = fmaxf(mx, om);
                s = s * __expf(mx - nm) + os * __expf(om - nm);
                mx = nm;
            }
            if ((lane & 3) == 0) {
                sRm[rl * 2 + wn] = mx;
                sRs[rl * 2 + wn] = s;
            }
        }
    }
    __syncthreads();
    if (tid < BM) {
        float ma = sRm[tid * 2], mb = sRm[tid * 2 + 1];
        float sa = sRs[tid * 2], sb = sRs[tid * 2 + 1];
        float nm = fmaxf(ma, mb);
        float s  = sa * __expf(ma - nm) + sb * __expf(mb - nm);
        g_pms[(m0 + tid) * NTP + blockIdx.y] = make_float2(nm, s);
    }
}

// ---------------- kernel 4: per-row logsumexp + picked (warp per row) --------
__global__ void lse_kernel(const float* __restrict__ out,
                           const int* __restrict__ labels) {
    int w = threadIdx.x >> 5, lane = threadIdx.x & 31;
    int b = blockIdx.x * 8 + w;        // grid 64 x 256 -> 512 rows
    float mx = -1e30f, s = 0.f;
    for (int t = lane; t < NT; t += 32) {
        float2 p = g_pms[b * NTP + t];
        float nm = fmaxf(mx, p.x);
        s = s * __expf(mx - nm) + p.y * __expf(p.x - nm);
        mx = nm;
    }
    #pragma unroll
    for (int o = 16; o; o >>= 1) {
        float om = __shfl_xor_sync(0xffffffffu, mx, o);
        float os = __shfl_xor_sync(0xffffffffu, s,  o);
        float nm = fmaxf(mx, om);
        s = s * __expf(mx - nm) + os * __expf(om - nm);
        mx = nm;
    }
    if (lane == 0) {
        float logz = mx + logf(s);
        g_lp[b] = logz - out[(long)b * N_ENT + labels[b]];
    }
}

// ---------------- kernel 5: mean loss -> tail of d_out ------------------------
__global__ void loss_kernel(float* __restrict__ out, int out_size) {
    int tid = threadIdx.x;             // 512
    __shared__ float red[BATCH];
    red[tid] = g_lp[tid];
    __syncthreads();
    for (int o = 256; o; o >>= 1) {
        if (tid < o) red[tid] += red[tid + o];
        __syncthreads();
    }
    __shared__ float loss_s;
    if (tid == 0) loss_s = red[0] / (float)BATCH;
    __syncthreads();
    const long base = (long)BATCH * N_ENT;
    for (long i = base + tid; i < (long)out_size; i += 512)
        out[i] = loss_s;
}

// ---------------- launch ------------------------------------------------------
extern "C" void kernel_launch(void* const* d_in, const int* in_sizes, int n_in,
                              void* d_out, int out_size) {
    const float* entity_emb = (const float*)d_in[0];
    const float* W1         = (const float*)d_in[1];
    const float* W2         = (const float*)d_in[2];
    const float* q          = (const float*)d_in[3];
    const float* soft_bias  = (const float*)d_in[4];
    const float* out_bias   = (const float*)d_in[5];
    const int*   seed_sets  = (const int*)d_in[6];   // jax default: int64 -> int32
    const int*   labels     = (const int*)d_in[7];
    float* out = (float*)d_out;

    const int dyn_bytes = 2 * 2 * SW * 4;            // 73,728 B
    static int configured = 0;
    if (!configured) {
        cudaFuncSetAttribute(gemm_kernel,
                             cudaFuncAttributeMaxDynamicSharedMemorySize, dyn_bytes);
        configured = 1;
    }

    prep_kernel<<<1, 128>>>(W1, W2, q, soft_bias);
    uemb_kernel<<<BATCH, 128>>>(entity_emb, seed_sets);
    gemm_kernel<<<dim3(BATCH / BM, NT), 256, dyn_bytes>>>(entity_emb, out_bias, out);
    lse_kernel<<<64, 256>>>(out, labels);
    loss_kernel<<<1, BATCH>>>(out, out_size);
}

// round 6
// speedup vs baseline: 1.1484x; 1.0559x over previous
#include <cuda_runtime.h>
#include <math.h>

#define N_ENT   64368
#define DIM     128
#define BATCH   512
#define SEQ     50
#define NTILE   503          // ceil(64368/128)
#define NTP     512          // padded partial stride
#define NGRP    38           // n-groups; grid = 4*38 = 152 persistent CTAs
#define CPAD    36           // smem row stride (words) within a 32-col chunk
#define CHW     (128 * CPAD) // words per chunk region (4608)
#define CHB     (CHW * 4)    // bytes per chunk region (18432)
#define TILEB   (4 * CHB)    // bytes per full 128x128 tile (73728)

// ---------------- scratch (device globals; no allocations allowed) ----------
__device__ float g_r1[DIM];
__device__ float g_r2[DIM];
__device__ float g_c;
__device__ __align__(128) float g_u[BATCH * DIM];
__device__ __align__(16) float2 g_pms[BATCH * NTP];
__device__ float g_lp[BATCH];

// ---------------- helpers ----------------------------------------------------
__device__ __forceinline__ unsigned f2tf(float x) {
    unsigned r;
    asm("cvt.rna.tf32.f32 %0, %1;" : "=r"(r) : "f"(x));
    return r;
}
__device__ __forceinline__ unsigned sptr(const void* p) {
    return (unsigned)__cvta_generic_to_shared(p);
}
__device__ __forceinline__ void cp_async16(unsigned dst, const void* src, int sz) {
    asm volatile("cp.async.cg.shared.global [%0], [%1], 16, %2;\n"
                 :: "r"(dst), "l"(src), "r"(sz));
}
__device__ __forceinline__ void cp_commit() { asm volatile("cp.async.commit_group;\n"); }
template <int N> __device__ __forceinline__ void cp_wait() {
    asm volatile("cp.async.wait_group %0;\n" :: "n"(N));
}
__device__ __forceinline__ void mma_tf32(float* d, const unsigned* a, unsigned b0, unsigned b1) {
    asm volatile(
        "mma.sync.aligned.m16n8k8.row.col.f32.tf32.tf32.f32 "
        "{%0,%1,%2,%3}, {%4,%5,%6,%7}, {%8,%9}, {%0,%1,%2,%3};\n"
        : "+f"(d[0]), "+f"(d[1]), "+f"(d[2]), "+f"(d[3])
        : "r"(a[0]), "r"(a[1]), "r"(a[2]), "r"(a[3]), "r"(b0), "r"(b1));
}

// ---------------- kernel 1: r1 = W1^T q, r2 = W2^T q, c = soft_bias * sum(q) -
__global__ void prep_kernel(const float* __restrict__ W1, const float* __restrict__ W2,
                            const float* __restrict__ q,  const float* __restrict__ soft_bias) {
    int d = threadIdx.x;               // 128 threads
    __shared__ float sq[DIM];
    __shared__ float red[DIM];
    sq[d] = q[d];
    __syncthreads();
    float r1 = 0.f, r2 = 0.f;
    #pragma unroll 8
    for (int e = 0; e < DIM; e++) {
        float qe = sq[e];
        r1 += qe * W1[e * DIM + d];
        r2 += qe * W2[e * DIM + d];
    }
    g_r1[d] = r1;
    g_r2[d] = r2;
    red[d] = sq[d];
    __syncthreads();
    for (int s = 64; s > 0; s >>= 1) {
        if (d < s) red[d] += red[d + s];
        __syncthreads();
    }
    if (d == 0) g_c = soft_bias[0] * red[0];
}

// ---------------- kernel 2: u_emb (tf32-rounded A operand) -------------------
__global__ void uemb_kernel(const float* __restrict__ emb,
                            const int* __restrict__ seeds) {
    int b = blockIdx.x;
    int d = threadIdx.x;               // 128 threads, thread = dim
    int warp = d >> 5, lane = d & 31;

    __shared__ float v[SEQ][DIM];
    __shared__ float att[SEQ];
    __shared__ float sr1[DIM], sr2[DIM];
    __shared__ float dn;

    sr1[d] = g_r1[d];
    sr2[d] = g_r2[d];

    float w = expf(-(float)(d & ~1) * (logf(10000.0f) / (float)DIM));
    bool odd = (d & 1);

    for (int l = 0; l < SEQ; l++) {
        int idx = seeds[b * SEQ + l];
        float arg = (float)l * w;
        float pe = (odd ? cosf(arg) : sinf(arg)) * 0.001f;
        v[l][d] = emb[(size_t)idx * DIM + d] + pe;
    }
    __syncthreads();

    for (int l = warp; l < SEQ; l += 4) {
        float p = sr1[lane]      * v[l][lane]
                + sr1[lane + 32] * v[l][lane + 32]
                + sr1[lane + 64] * v[l][lane + 64]
                + sr1[lane + 96] * v[l][lane + 96];
        #pragma unroll
        for (int o = 16; o; o >>= 1) p += __shfl_xor_sync(0xffffffffu, p, o);
        if (lane == 0) att[l] = p;
    }
    if (warp == 0) {
        float p = sr2[lane]      * v[SEQ - 1][lane]
                + sr2[lane + 32] * v[SEQ - 1][lane + 32]
                + sr2[lane + 64] * v[SEQ - 1][lane + 64]
                + sr2[lane + 96] * v[SEQ - 1][lane + 96];
        #pragma unroll
        for (int o = 16; o; o >>= 1) p += __shfl_xor_sync(0xffffffffu, p, o);
        if (lane == 0) dn = p + g_c;
    }
    __syncthreads();
    if (d < SEQ) att[d] += dn;
    __syncthreads();

    float acc = 0.f;
    #pragma unroll 10
    for (int l = 0; l < SEQ; l++) acc += att[l] * v[l][d];
    g_u[b * DIM + d] = __uint_as_float(f2tf(acc));
}

// ---------------- kernel 3: persistent mma.sync GEMM + fused streaming LSE ---
// grid = 152 (4 m-tiles x 38 n-groups), 1 CTA/SM, 256 threads.
// smem: A tile [73728B] | B stage0 [73728B] | B stage1 [73728B]
// A fragments hoisted to registers for the whole CTA lifetime.
extern __shared__ __align__(16) unsigned char dynraw[];

__global__ void __launch_bounds__(256, 1)
gemm_kernel(const float* __restrict__ emb, const float* __restrict__ out_bias,
            float* __restrict__ out) {
    __shared__ float sBias[128];
    __shared__ float sRm[128][2];
    __shared__ float sRs[128][2];

    const int tid  = threadIdx.x;
    const int warp = tid >> 5, lane = tid & 31;
    const int wm   = warp & 3;          // warp m index (4)
    const int wn   = warp >> 2;         // warp n index (2)
    const int m0   = (blockIdx.x & 3) * 128;
    const int grp  = blockIdx.x >> 2;   // 0..37

    const unsigned aBase  = sptr(dynraw);
    const unsigned bBase0 = aBase + TILEB;
    const unsigned bBase1 = aBase + 2 * TILEB;

    const int lr  = tid >> 3;   // row 0..31 (stride 32)
    const int seg = tid & 7;    // 16B segment within 32-float chunk row

    // ---- load A tile once (4 chunk regions of [128][CPAD] words) -----------
    #pragma unroll
    for (int c = 0; c < 4; c++) {
        #pragma unroll
        for (int k = 0; k < 4; k++) {
            int r = lr + k * 32;
            unsigned dst = aBase + c * CHB + (unsigned)(r * CPAD * 4 + seg * 16);
            cp_async16(dst, &g_u[(m0 + r) * DIM + c * 32 + seg * 4], 16);
        }
    }

    auto load_B = [&](int n, unsigned bb) {
        #pragma unroll
        for (int c = 0; c < 4; c++) {
            #pragma unroll
            for (int k = 0; k < 4; k++) {
                int r  = lr + k * 32;
                int g  = n * 128 + r;
                int gc = g < N_ENT ? g : 0;
                unsigned dst = bb + c * CHB + (unsigned)(r * CPAD * 4 + seg * 16);
                cp_async16(dst, &emb[(size_t)gc * DIM + c * 32 + seg * 4],
                           g < N_ENT ? 16 : 0);
            }
        }
    };

    load_B(grp, bBase0);
    cp_commit();                         // group: A + B(tile0)
    cp_wait<0>();
    __syncthreads();

    // ---- hoist A fragments into registers (fixed for all n-tiles) ----------
    unsigned aF[16][2][4];
    {
        const unsigned* sA = (const unsigned*)dynraw;
        const int ar = wm * 32 + (lane >> 2);
        #pragma unroll
        for (int ks = 0; ks < 16; ks++) {
            const int ch = ks >> 2;
            const int ac = (ks & 3) * 8 + (lane & 3);
            #pragma unroll
            for (int mf = 0; mf < 2; mf++) {
                int r = ar + mf * 16;
                aF[ks][mf][0] = sA[ch * CHW + r * CPAD + ac];
                aF[ks][mf][1] = sA[ch * CHW + (r + 8) * CPAD + ac];
                aF[ks][mf][2] = sA[ch * CHW + r * CPAD + ac + 4];
                aF[ks][mf][3] = sA[ch * CHW + (r + 8) * CPAD + ac + 4];
            }
        }
    }

    int it = 0;
    for (int n = grp; n < NTILE; n += NGRP, it++) {
        const unsigned curB = (it & 1) ? bBase1 : bBase0;
        const unsigned nxtB = (it & 1) ? bBase0 : bBase1;
        const bool have_next = (n + NGRP) < NTILE;

        if (have_next) { load_B(n + NGRP, nxtB); cp_commit(); cp_wait<1>(); }
        else           { cp_wait<0>(); }
        __syncthreads();                 // current B resident

        if (tid < 128) {
            int g = n * 128 + tid;
            sBias[tid] = (g < N_ENT) ? out_bias[g] : 0.f;
        }

        // ---- mainloop: full K, no syncs ------------------------------------
        float acc[2][8][4];
        #pragma unroll
        for (int i = 0; i < 2; i++)
            #pragma unroll
            for (int j = 0; j < 8; j++)
                #pragma unroll
                for (int k = 0; k < 4; k++) acc[i][j][k] = 0.f;

        const unsigned* sB = (const unsigned*)(dynraw + (curB - aBase));
        #pragma unroll
        for (int ks = 0; ks < 16; ks++) {
            const int ch = ks >> 2;
            const int k0 = (ks & 3) * 8 + (lane & 3);
            #pragma unroll
            for (int nf = 0; nf < 8; nf++) {
                int br = wn * 64 + nf * 8 + (lane >> 2);
                unsigned b0 = sB[ch * CHW + br * CPAD + k0];
                unsigned b1 = sB[ch * CHW + br * CPAD + k0 + 4];
                mma_tf32(acc[0][nf], aF[ks][0], b0, b1);
                mma_tf32(acc[1][nf], aF[ks][1], b0, b1);
            }
        }
        __syncthreads();                 // sBias visible; mainloop done

        // ---- epilogue: bias, store, streaming (max, sumexp) ----------------
        const float NEG = -1e30f;
        #pragma unroll
        for (int mf = 0; mf < 2; mf++) {
            #pragma unroll
            for (int h = 0; h < 2; h++) {
                const int rl = wm * 32 + mf * 16 + h * 8 + (lane >> 2);
                const size_t grow = (size_t)(m0 + rl) * N_ENT;
                float mx = NEG;
                #pragma unroll
                for (int nf = 0; nf < 8; nf++) {
                    int c = wn * 64 + nf * 8 + ((lane & 3) << 1);
                    int g = n * 128 + c;
                    float v0 = acc[mf][nf][2 * h]     + sBias[c];
                    float v1 = acc[mf][nf][2 * h + 1] + sBias[c + 1];
                    if (g + 1 < N_ENT) {
                        *(float2*)&out[grow + g] = make_float2(v0, v1);
                    } else if (g < N_ENT) {
                        out[grow + g] = v0;
                        v1 = NEG;
                    } else {
                        v0 = NEG; v1 = NEG;
                    }
                    acc[mf][nf][2 * h]     = v0;
                    acc[mf][nf][2 * h + 1] = v1;
                    mx = fmaxf(mx, fmaxf(v0, v1));
                }
                float s = 0.f;
                #pragma unroll
                for (int nf = 0; nf < 8; nf++)
                    s += __expf(acc[mf][nf][2 * h] - mx)
                       + __expf(acc[mf][nf][2 * h + 1] - mx);
                #pragma unroll
                for (int off = 1; off <= 2; off <<= 1) {
                    float om = __shfl_xor_sync(0xffffffffu, mx, off);
                    float os = __shfl_xor_sync(0xffffffffu, s,  off);
                    float nm = fmaxf(mx, om);
                    s = s * __expf(mx - nm) + os * __expf(om - nm);
                    mx = nm;
                }
                if ((lane & 3) == 0) {
                    sRm[rl][wn] = mx;
                    sRs[rl][wn] = s;
                }
            }
        }
        __syncthreads();
        if (tid < 128) {
            float ma = sRm[tid][0], mb = sRm[tid][1];
            float sa = sRs[tid][0], sb = sRs[tid][1];
            float nm = fmaxf(ma, mb);
            float ss = sa * __expf(ma - nm) + sb * __expf(mb - nm);
            g_pms[(m0 + tid) * NTP + n] = make_float2(nm, ss);
        }
        __syncthreads();                 // protect sRm/sRs reuse
    }
}

// ---------------- kernel 4: per-row logsumexp + picked (4-stream MLP) --------
__global__ void lse_kernel(const float* __restrict__ out,
                           const int* __restrict__ labels) {
    int w = threadIdx.x >> 5, lane = threadIdx.x & 31;
    int b = blockIdx.x * 8 + w;        // grid 64 x 256 -> 512 rows
    float mx0 = -1e30f, mx1 = -1e30f, mx2 = -1e30f, mx3 = -1e30f;
    float s0 = 0.f, s1 = 0.f, s2 = 0.f, s3 = 0.f;
    for (int t0 = 0; t0 < NTILE; t0 += 128) {
        int t = t0 + lane;
        if (t < NTILE) {
            float2 p = g_pms[b * NTP + t];
            float nm = fmaxf(mx0, p.x);
            s0 = s0 * __expf(mx0 - nm) + p.y * __expf(p.x - nm); mx0 = nm;
        }
        if (t + 32 < NTILE) {
            float2 p = g_pms[b * NTP + t + 32];
            float nm = fmaxf(mx1, p.x);
            s1 = s1 * __expf(mx1 - nm) + p.y * __expf(p.x - nm); mx1 = nm;
        }
        if (t + 64 < NTILE) {
            float2 p = g_pms[b * NTP + t + 64];
            float nm = fmaxf(mx2, p.x);
            s2 = s2 * __expf(mx2 - nm) + p.y * __expf(p.x - nm); mx2 = nm;
        }
        if (t + 96 < NTILE) {
            float2 p = g_pms[b * NTP + t + 96];
            float nm = fmaxf(mx3, p.x);
            s3 = s3 * __expf(mx3 - nm) + p.y * __expf(p.x - nm); mx3 = nm;
        }
    }
    float nm01 = fmaxf(mx0, mx1);
    float s01  = s0 * __expf(mx0 - nm01) + s1 * __expf(mx1 - nm01);
    float nm23 = fmaxf(mx2, mx3);
    float s23  = s2 * __expf(mx2 - nm23) + s3 * __expf(mx3 - nm23);
    float mx   = fmaxf(nm01, nm23);
    float s    = s01 * __expf(nm01 - mx) + s23 * __expf(nm23 - mx);
    #pragma unroll
    for (int o = 16; o; o >>= 1) {
        float om = __shfl_xor_sync(0xffffffffu, mx, o);
        float os = __shfl_xor_sync(0xffffffffu, s,  o);
        float nm = fmaxf(mx, om);
        s = s * __expf(mx - nm) + os * __expf(om - nm);
        mx = nm;
    }
    if (lane == 0) {
        float logz = mx + logf(s);
        g_lp[b] = logz - out[(size_t)b * N_ENT + labels[b]];
    }
}

// ---------------- kernel 5: mean loss -> tail of d_out ------------------------
__global__ void loss_kernel(float* __restrict__ out, int out_size) {
    int tid = threadIdx.x;             // 512
    __shared__ float red[BATCH];
    red[tid] = g_lp[tid];
    __syncthreads();
    for (int o = 256; o; o >>= 1) {
        if (tid < o) red[tid] += red[tid + o];
        __syncthreads();
    }
    __shared__ float loss_s;
    if (tid == 0) loss_s = red[0] / (float)BATCH;
    __syncthreads();
    const long base = (long)BATCH * N_ENT;
    for (long i = base + tid; i < (long)out_size; i += 512)
        out[i] = loss_s;
}

// ---------------- launch ------------------------------------------------------
extern "C" void kernel_launch(void* const* d_in, const int* in_sizes, int n_in,
                              void* d_out, int out_size) {
    const float* entity_emb = (const float*)d_in[0];
    const float* W1         = (const float*)d_in[1];
    const float* W2         = (const float*)d_in[2];
    const float* q          = (const float*)d_in[3];
    const float* soft_bias  = (const float*)d_in[4];
    const float* out_bias   = (const float*)d_in[5];
    const int*   seed_sets  = (const int*)d_in[6];   // jax default: int64 -> int32
    const int*   labels     = (const int*)d_in[7];
    float* out = (float*)d_out;

    const int dyn_bytes = 3 * TILEB;                 // 221,184 B
    cudaFuncSetAttribute(gemm_kernel,
                         cudaFuncAttributeMaxDynamicSharedMemorySize, dyn_bytes);

    prep_kernel<<<1, 128>>>(W1, W2, q, soft_bias);
    uemb_kernel<<<BATCH, 128>>>(entity_emb, seed_sets);
    gemm_kernel<<<4 * NGRP, 256, dyn_bytes>>>(entity_emb, out_bias, out);
    lse_kernel<<<64, 256>>>(out, labels);
    loss_kernel<<<1, BATCH>>>(out, out_size);
}

// round 7
// speedup vs baseline: 1.1509x; 1.0022x over previous
#include <cuda_runtime.h>
#include <math.h>

#define N_ENT   64368
#define DIM     128
#define BATCH   512
#define SEQ     50
#define NTILE   503          // ceil(64368/128)
#define NTP     512          // padded partial stride
#define NGRP    38           // n-groups; grid = 4*38 = 152 persistent CTAs
#define CPAD    36           // smem row stride (words) within a 32-col chunk
#define CHW     (128 * CPAD) // words per chunk region (4608)
#define CHB     (CHW * 4)    // bytes per chunk region (18432)
#define TILEB   (4 * CHB)    // bytes per full 128x128 tile (73728)

// ---------------- scratch (device globals; no allocations allowed) ----------
__device__ float g_r1[DIM];
__device__ float g_r2[DIM];
__device__ float g_c;
__device__ __align__(128) float g_u[BATCH * DIM];
__device__ __align__(16) float2 g_pms[BATCH * NTP];
__device__ float g_lp[BATCH];

// ---------------- helpers ----------------------------------------------------
__device__ __forceinline__ unsigned f2tf(float x) {
    unsigned r;
    asm("cvt.rna.tf32.f32 %0, %1;" : "=r"(r) : "f"(x));
    return r;
}
__device__ __forceinline__ unsigned sptr(const void* p) {
    return (unsigned)__cvta_generic_to_shared(p);
}
__device__ __forceinline__ void cp_async16(unsigned dst, const void* src, int sz) {
    asm volatile("cp.async.cg.shared.global [%0], [%1], 16, %2;\n"
                 :: "r"(dst), "l"(src), "r"(sz));
}
__device__ __forceinline__ void cp_commit() { asm volatile("cp.async.commit_group;\n"); }
template <int N> __device__ __forceinline__ void cp_wait() {
    asm volatile("cp.async.wait_group %0;\n" :: "n"(N));
}
__device__ __forceinline__ void mma_tf32(float* d, const unsigned* a, unsigned b0, unsigned b1) {
    asm volatile(
        "mma.sync.aligned.m16n8k8.row.col.f32.tf32.tf32.f32 "
        "{%0,%1,%2,%3}, {%4,%5,%6,%7}, {%8,%9}, {%0,%1,%2,%3};\n"
        : "+f"(d[0]), "+f"(d[1]), "+f"(d[2]), "+f"(d[3])
        : "r"(a[0]), "r"(a[1]), "r"(a[2]), "r"(a[3]), "r"(b0), "r"(b1));
}

// ---------------- kernel 1: r1 = W1^T q, r2 = W2^T q, c = soft_bias * sum(q) -
__global__ void prep_kernel(const float* __restrict__ W1, const float* __restrict__ W2,
                            const float* __restrict__ q,  const float* __restrict__ soft_bias) {
    int d = threadIdx.x;               // 128 threads
    __shared__ float sq[DIM];
    __shared__ float red[DIM];
    sq[d] = q[d];
    __syncthreads();
    float r1 = 0.f, r2 = 0.f;
    #pragma unroll 8
    for (int e = 0; e < DIM; e++) {
        float qe = sq[e];
        r1 += qe * W1[e * DIM + d];
        r2 += qe * W2[e * DIM + d];
    }
    g_r1[d] = r1;
    g_r2[d] = r2;
    red[d] = sq[d];
    __syncthreads();
    for (int s = 64; s > 0; s >>= 1) {
        if (d < s) red[d] += red[d + s];
        __syncthreads();
    }
    if (d == 0) g_c = soft_bias[0] * red[0];
}

// ---------------- kernel 2: u_emb (tf32-rounded A operand) -------------------
__global__ void uemb_kernel(const float* __restrict__ emb,
                            const int* __restrict__ seeds) {
    int b = blockIdx.x;
    int d = threadIdx.x;               // 128 threads, thread = dim
    int warp = d >> 5, lane = d & 31;

    __shared__ float v[SEQ][DIM];
    __shared__ float att[SEQ];
    __shared__ float sr1[DIM], sr2[DIM];
    __shared__ float dn;

    sr1[d] = g_r1[d];
    sr2[d] = g_r2[d];

    float w = expf(-(float)(d & ~1) * (logf(10000.0f) / (float)DIM));
    bool odd = (d & 1);

    for (int l = 0; l < SEQ; l++) {
        int idx = seeds[b * SEQ + l];
        float arg = (float)l * w;
        float pe = (odd ? cosf(arg) : sinf(arg)) * 0.001f;
        v[l][d] = emb[(size_t)idx * DIM + d] + pe;
    }
    __syncthreads();

    for (int l = warp; l < SEQ; l += 4) {
        float p = sr1[lane]      * v[l][lane]
                + sr1[lane + 32] * v[l][lane + 32]
                + sr1[lane + 64] * v[l][lane + 64]
                + sr1[lane + 96] * v[l][lane + 96];
        #pragma unroll
        for (int o = 16; o; o >>= 1) p += __shfl_xor_sync(0xffffffffu, p, o);
        if (lane == 0) att[l] = p;
    }
    if (warp == 0) {
        float p = sr2[lane]      * v[SEQ - 1][lane]
                + sr2[lane + 32] * v[SEQ - 1][lane + 32]
                + sr2[lane + 64] * v[SEQ - 1][lane + 64]
                + sr2[lane + 96] * v[SEQ - 1][lane + 96];
        #pragma unroll
        for (int o = 16; o; o >>= 1) p += __shfl_xor_sync(0xffffffffu, p, o);
        if (lane == 0) dn = p + g_c;
    }
    __syncthreads();
    if (d < SEQ) att[d] += dn;
    __syncthreads();

    float acc = 0.f;
    #pragma unroll 10
    for (int l = 0; l < SEQ; l++) acc += att[l] * v[l][d];
    g_u[b * DIM + d] = __uint_as_float(f2tf(acc));
}

// ---------------- kernel 3: persistent mma.sync GEMM + fused streaming LSE ---
// grid = 152 (4 m-tiles x 38 n-groups), 1 CTA/SM, 256 threads.
// smem: A tile [73728B] | B stage0 [73728B] | B stage1 [73728B]
// A fragments hoisted to registers for the whole CTA lifetime.
extern __shared__ __align__(16) unsigned char dynraw[];

__global__ void __launch_bounds__(256, 1)
gemm_kernel(const float* __restrict__ emb, const float* __restrict__ out_bias,
            float* __restrict__ out) {
    __shared__ float sBias[128];
    __shared__ float sRm[128][2];
    __shared__ float sRs[128][2];

    const int tid  = threadIdx.x;
    const int warp = tid >> 5, lane = tid & 31;
    const int wm   = warp & 3;          // warp m index (4)
    const int wn   = warp >> 2;         // warp n index (2)
    const int m0   = (blockIdx.x & 3) * 128;
    const int grp  = blockIdx.x >> 2;   // 0..37

    const unsigned aBase  = sptr(dynraw);
    const unsigned bBase0 = aBase + TILEB;
    const unsigned bBase1 = aBase + 2 * TILEB;

    const int lr  = tid >> 3;   // row 0..31 (stride 32)
    const int seg = tid & 7;    // 16B segment within 32-float chunk row

    // ---- load A tile once (4 chunk regions of [128][CPAD] words) -----------
    #pragma unroll
    for (int c = 0; c < 4; c++) {
        #pragma unroll
        for (int k = 0; k < 4; k++) {
            int r = lr + k * 32;
            unsigned dst = aBase + c * CHB + (unsigned)(r * CPAD * 4 + seg * 16);
            cp_async16(dst, &g_u[(m0 + r) * DIM + c * 32 + seg * 4], 16);
        }
    }

    auto load_B = [&](int n, unsigned bb) {
        #pragma unroll
        for (int c = 0; c < 4; c++) {
            #pragma unroll
            for (int k = 0; k < 4; k++) {
                int r  = lr + k * 32;
                int g  = n * 128 + r;
                int gc = g < N_ENT ? g : 0;
                unsigned dst = bb + c * CHB + (unsigned)(r * CPAD * 4 + seg * 16);
                cp_async16(dst, &emb[(size_t)gc * DIM + c * 32 + seg * 4],
                           g < N_ENT ? 16 : 0);
            }
        }
    };

    load_B(grp, bBase0);
    cp_commit();                         // group: A + B(tile0)
    cp_wait<0>();
    __syncthreads();

    // ---- hoist A fragments into registers (fixed for all n-tiles) ----------
    unsigned aF[16][2][4];
    {
        const unsigned* sA = (const unsigned*)dynraw;
        const int ar = wm * 32 + (lane >> 2);
        #pragma unroll
        for (int ks = 0; ks < 16; ks++) {
            const int ch = ks >> 2;
            const int ac = (ks & 3) * 8 + (lane & 3);
            #pragma unroll
            for (int mf = 0; mf < 2; mf++) {
                int r = ar + mf * 16;
                aF[ks][mf][0] = sA[ch * CHW + r * CPAD + ac];
                aF[ks][mf][1] = sA[ch * CHW + (r + 8) * CPAD + ac];
                aF[ks][mf][2] = sA[ch * CHW + r * CPAD + ac + 4];
                aF[ks][mf][3] = sA[ch * CHW + (r + 8) * CPAD + ac + 4];
            }
        }
    }

    int it = 0;
    for (int n = grp; n < NTILE; n += NGRP, it++) {
        const unsigned curB = (it & 1) ? bBase1 : bBase0;
        const unsigned nxtB = (it & 1) ? bBase0 : bBase1;
        const bool have_next = (n + NGRP) < NTILE;

        if (have_next) { load_B(n + NGRP, nxtB); cp_commit(); cp_wait<1>(); }
        else           { cp_wait<0>(); }
        __syncthreads();                 // current B resident

        if (tid < 128) {
            int g = n * 128 + tid;
            sBias[tid] = (g < N_ENT) ? out_bias[g] : 0.f;
        }

        // ---- mainloop: full K, no syncs ------------------------------------
        float acc[2][8][4];
        #pragma unroll
        for (int i = 0; i < 2; i++)
            #pragma unroll
            for (int j = 0; j < 8; j++)
                #pragma unroll
                for (int k = 0; k < 4; k++) acc[i][j][k] = 0.f;

        const unsigned* sB = (const unsigned*)(dynraw + (curB - aBase));
        #pragma unroll
        for (int ks = 0; ks < 16; ks++) {
            const int ch = ks >> 2;
            const int k0 = (ks & 3) * 8 + (lane & 3);
            #pragma unroll
            for (int nf = 0; nf < 8; nf++) {
                int br = wn * 64 + nf * 8 + (lane >> 2);
                unsigned b0 = sB[ch * CHW + br * CPAD + k0];
                unsigned b1 = sB[ch * CHW + br * CPAD + k0 + 4];
                mma_tf32(acc[0][nf], aF[ks][0], b0, b1);
                mma_tf32(acc[1][nf], aF[ks][1], b0, b1);
            }
        }
        __syncthreads();                 // sBias visible; mainloop done

        // ---- epilogue: bias, store, streaming (max, sumexp) ----------------
        const float NEG = -1e30f;
        #pragma unroll
        for (int mf = 0; mf < 2; mf++) {
            #pragma unroll
            for (int h = 0; h < 2; h++) {
                const int rl = wm * 32 + mf * 16 + h * 8 + (lane >> 2);
                const size_t grow = (size_t)(m0 + rl) * N_ENT;
                float mx = NEG;
                #pragma unroll
                for (int nf = 0; nf < 8; nf++) {
                    int c = wn * 64 + nf * 8 + ((lane & 3) << 1);
                    int g = n * 128 + c;
                    float v0 = acc[mf][nf][2 * h]     + sBias[c];
                    float v1 = acc[mf][nf][2 * h + 1] + sBias[c + 1];
                    if (g + 1 < N_ENT) {
                        *(float2*)&out[grow + g] = make_float2(v0, v1);
                    } else if (g < N_ENT) {
                        out[grow + g] = v0;
                        v1 = NEG;
                    } else {
                        v0 = NEG; v1 = NEG;
                    }
                    acc[mf][nf][2 * h]     = v0;
                    acc[mf][nf][2 * h + 1] = v1;
                    mx = fmaxf(mx, fmaxf(v0, v1));
                }
                float s = 0.f;
                #pragma unroll
                for (int nf = 0; nf < 8; nf++)
                    s += __expf(acc[mf][nf][2 * h] - mx)
                       + __expf(acc[mf][nf][2 * h + 1] - mx);
                #pragma unroll
                for (int off = 1; off <= 2; off <<= 1) {
                    float om = __shfl_xor_sync(0xffffffffu, mx, off);
                    float os = __shfl_xor_sync(0xffffffffu, s,  off);
                    float nm = fmaxf(mx, om);
                    s = s * __expf(mx - nm) + os * __expf(om - nm);
                    mx = nm;
                }
                if ((lane & 3) == 0) {
                    sRm[rl][wn] = mx;
                    sRs[rl][wn] = s;
                }
            }
        }
        __syncthreads();
        if (tid < 128) {
            float ma = sRm[tid][0], mb = sRm[tid][1];
            float sa = sRs[tid][0], sb = sRs[tid][1];
            float nm = fmaxf(ma, mb);
            float ss = sa * __expf(ma - nm) + sb * __expf(mb - nm);
            g_pms[(m0 + tid) * NTP + n] = make_float2(nm, ss);
        }
        __syncthreads();                 // protect sRm/sRs reuse
    }
}

// ---------------- kernel 4: per-row logsumexp + picked (4-stream MLP) --------
__global__ void lse_kernel(const float* __restrict__ out,
                           const int* __restrict__ labels) {
    int w = threadIdx.x >> 5, lane = threadIdx.x & 31;
    int b = blockIdx.x * 8 + w;        // grid 64 x 256 -> 512 rows
    float mx0 = -1e30f, mx1 = -1e30f, mx2 = -1e30f, mx3 = -1e30f;
    float s0 = 0.f, s1 = 0.f, s2 = 0.f, s3 = 0.f;
    for (int t0 = 0; t0 < NTILE; t0 += 128) {
        int t = t0 + lane;
        if (t < NTILE) {
            float2 p = g_pms[b * NTP + t];
            float nm = fmaxf(mx0, p.x);
            s0 = s0 * __expf(mx0 - nm) + p.y * __expf(p.x - nm); mx0 = nm;
        }
        if (t + 32 < NTILE) {
            float2 p = g_pms[b * NTP + t + 32];
            float nm = fmaxf(mx1, p.x);
            s1 = s1 * __expf(mx1 - nm) + p.y * __expf(p.x - nm); mx1 = nm;
        }
        if (t + 64 < NTILE) {
            float2 p = g_pms[b * NTP + t + 64];
            float nm = fmaxf(mx2, p.x);
            s2 = s2 * __expf(mx2 - nm) + p.y * __expf(p.x - nm); mx2 = nm;
        }
        if (t + 96 < NTILE) {
            float2 p = g_pms[b * NTP + t + 96];
            float nm = fmaxf(mx3, p.x);
            s3 = s3 * __expf(mx3 - nm) + p.y * __expf(p.x - nm); mx3 = nm;
        }
    }
    float nm01 = fmaxf(mx0, mx1);
    float s01  = s0 * __expf(mx0 - nm01) + s1 * __expf(mx1 - nm01);
    float nm23 = fmaxf(mx2, mx3);
    float s23  = s2 * __expf(mx2 - nm23) + s3 * __expf(mx3 - nm23);
    float mx   = fmaxf(nm01, nm23);
    float s    = s01 * __expf(nm01 - mx) + s23 * __expf(nm23 - mx);
    #pragma unroll
    for (int o = 16; o; o >>= 1) {
        float om = __shfl_xor_sync(0xffffffffu, mx, o);
        float os = __shfl_xor_sync(0xffffffffu, s,  o);
        float nm = fmaxf(mx, om);
        s = s * __expf(mx - nm) + os * __expf(om - nm);
        mx = nm;
    }
    if (lane == 0) {
        float logz = mx + logf(s);
        g_lp[b] = logz - out[(size_t)b * N_ENT + labels[b]];
    }
}

// ---------------- kernel 5: mean loss -> tail of d_out ------------------------
__global__ void loss_kernel(float* __restrict__ out, int out_size) {
    int tid = threadIdx.x;             // 512
    __shared__ float red[BATCH];
    red[tid] = g_lp[tid];
    __syncthreads();
    for (int o = 256; o; o >>= 1) {
        if (tid < o) red[tid] += red[tid + o];
        __syncthreads();
    }
    __shared__ float loss_s;
    if (tid == 0) loss_s = red[0] / (float)BATCH;
    __syncthreads();
    const long base = (long)BATCH * N_ENT;
    for (long i = base + tid; i < (long)out_size; i += 512)
        out[i] = loss_s;
}

// ---------------- launch ------------------------------------------------------
extern "C" void kernel_launch(void* const* d_in, const int* in_sizes, int n_in,
                              void* d_out, int out_size) {
    const float* entity_emb = (const float*)d_in[0];
    const float* W1         = (const float*)d_in[1];
    const float* W2         = (const float*)d_in[2];
    const float* q          = (const float*)d_in[3];
    const float* soft_bias  = (const float*)d_in[4];
    const float* out_bias   = (const float*)d_in[5];
    const int*   seed_sets  = (const int*)d_in[6];   // jax default: int64 -> int32
    const int*   labels     = (const int*)d_in[7];
    float* out = (float*)d_out;

    const int dyn_bytes = 3 * TILEB;                 // 221,184 B
    cudaFuncSetAttribute(gemm_kernel,
                         cudaFuncAttributeMaxDynamicSharedMemorySize, dyn_bytes);

    prep_kernel<<<1, 128>>>(W1, W2, q, soft_bias);
    uemb_kernel<<<BATCH, 128>>>(entity_emb, seed_sets);
    gemm_kernel<<<4 * NGRP, 256, dyn_bytes>>>(entity_emb, out_bias, out);
    lse_kernel<<<64, 256>>>(out, labels);
    loss_kernel<<<1, BATCH>>>(out, out_size);
}

// round 8
// speedup vs baseline: 1.3887x; 1.2066x over previous
#include <cuda_runtime.h>
#include <cuda_fp16.h>
#include <math.h>

#define N_ENT   64368
#define DIM     128
#define BATCH   512
#define SEQ     50
#define NTILE   503          // ceil(64368/128)
#define NTP     512          // padded partial stride
#define NGRP    38           // n-groups; grid = 4*38 = 152 persistent CTAs
#define RSTRIDE 136          // halves per smem row (272B, pad for conflict-free frags)
#define RSW     68           // words per smem row
#define TILEB   (128 * 272)  // bytes per 128x128 half tile (34816)

// ---------------- scratch (device globals; no allocations allowed) ----------
__device__ float g_r1[DIM];
__device__ float g_r2[DIM];
__device__ float g_c;
__device__ __align__(16) __half g_uh[BATCH * DIM];
__device__ __align__(16) __half g_eh[N_ENT * DIM];     // fp16 entity_emb (16.5MB)
__device__ __align__(16) float2 g_pms[BATCH * NTP];
__device__ float g_lp[BATCH];

// ---------------- helpers ----------------------------------------------------
__device__ __forceinline__ unsigned sptr(const void* p) {
    return (unsigned)__cvta_generic_to_shared(p);
}
__device__ __forceinline__ void cp_async16(unsigned dst, const void* src, int sz) {
    asm volatile("cp.async.cg.shared.global [%0], [%1], 16, %2;\n"
                 :: "r"(dst), "l"(src), "r"(sz));
}
__device__ __forceinline__ void cp_commit() { asm volatile("cp.async.commit_group;\n"); }
template <int N> __device__ __forceinline__ void cp_wait() {
    asm volatile("cp.async.wait_group %0;\n" :: "n"(N));
}
__device__ __forceinline__ void mma_f16(float* d, const unsigned* a, unsigned b0, unsigned b1) {
    asm volatile(
        "mma.sync.aligned.m16n8k16.row.col.f32.f16.f16.f32 "
        "{%0,%1,%2,%3}, {%4,%5,%6,%7}, {%8,%9}, {%0,%1,%2,%3};\n"
        : "+f"(d[0]), "+f"(d[1]), "+f"(d[2]), "+f"(d[3])
        : "r"(a[0]), "r"(a[1]), "r"(a[2]), "r"(a[3]), "r"(b0), "r"(b1));
}

// ---------------- kernel 0: entity_emb f32 -> f16 ----------------------------
// 8,239,104 elems; 8 per thread; grid 4023 x 256.
__global__ void econv_kernel(const float* __restrict__ emb) {
    size_t base = ((size_t)blockIdx.x * blockDim.x + threadIdx.x) * 8;
    float4 a = *(const float4*)&emb[base];
    float4 b = *(const float4*)&emb[base + 4];
    __half2 h[4];
    h[0] = __floats2half2_rn(a.x, a.y);
    h[1] = __floats2half2_rn(a.z, a.w);
    h[2] = __floats2half2_rn(b.x, b.y);
    h[3] = __floats2half2_rn(b.z, b.w);
    *(uint4*)&g_eh[base] = *(uint4*)h;
}

// ---------------- kernel 1: r1 = W1^T q, r2 = W2^T q, c = soft_bias * sum(q) -
__global__ void prep_kernel(const float* __restrict__ W1, const float* __restrict__ W2,
                            const float* __restrict__ q,  const float* __restrict__ soft_bias) {
    int d = threadIdx.x;               // 128 threads
    __shared__ float sq[DIM];
    __shared__ float red[DIM];
    sq[d] = q[d];
    __syncthreads();
    float r1 = 0.f, r2 = 0.f;
    #pragma unroll 8
    for (int e = 0; e < DIM; e++) {
        float qe = sq[e];
        r1 += qe * W1[e * DIM + d];
        r2 += qe * W2[e * DIM + d];
    }
    g_r1[d] = r1;
    g_r2[d] = r2;
    red[d] = sq[d];
    __syncthreads();
    for (int s = 64; s > 0; s >>= 1) {
        if (d < s) red[d] += red[d + s];
        __syncthreads();
    }
    if (d == 0) g_c = soft_bias[0] * red[0];
}

// ---------------- kernel 2: u_emb (emitted as fp16 A operand) ----------------
__global__ void uemb_kernel(const float* __restrict__ emb,
                            const int* __restrict__ seeds) {
    int b = blockIdx.x;
    int d = threadIdx.x;               // 128 threads, thread = dim
    int warp = d >> 5, lane = d & 31;

    __shared__ float v[SEQ][DIM];
    __shared__ float att[SEQ];
    __shared__ float sr1[DIM], sr2[DIM];
    __shared__ float dn;

    sr1[d] = g_r1[d];
    sr2[d] = g_r2[d];

    float w = expf(-(float)(d & ~1) * (logf(10000.0f) / (float)DIM));
    bool odd = (d & 1);

    for (int l = 0; l < SEQ; l++) {
        int idx = seeds[b * SEQ + l];
        float arg = (float)l * w;
        float pe = (odd ? cosf(arg) : sinf(arg)) * 0.001f;
        v[l][d] = emb[(size_t)idx * DIM + d] + pe;
    }
    __syncthreads();

    for (int l = warp; l < SEQ; l += 4) {
        float p = sr1[lane]      * v[l][lane]
                + sr1[lane + 32] * v[l][lane + 32]
                + sr1[lane + 64] * v[l][lane + 64]
                + sr1[lane + 96] * v[l][lane + 96];
        #pragma unroll
        for (int o = 16; o; o >>= 1) p += __shfl_xor_sync(0xffffffffu, p, o);
        if (lane == 0) att[l] = p;
    }
    if (warp == 0) {
        float p = sr2[lane]      * v[SEQ - 1][lane]
                + sr2[lane + 32] * v[SEQ - 1][lane + 32]
                + sr2[lane + 64] * v[SEQ - 1][lane + 64]
                + sr2[lane + 96] * v[SEQ - 1][lane + 96];
        #pragma unroll
        for (int o = 16; o; o >>= 1) p += __shfl_xor_sync(0xffffffffu, p, o);
        if (lane == 0) dn = p + g_c;
    }
    __syncthreads();
    if (d < SEQ) att[d] += dn;
    __syncthreads();

    float acc = 0.f;
    #pragma unroll 10
    for (int l = 0; l < SEQ; l++) acc += att[l] * v[l][d];
    g_uh[b * DIM + d] = __float2half_rn(acc);
}

// ---------------- kernel 3: persistent fp16 mma GEMM + fused streaming LSE ---
// grid = 152 (4 m-tiles x 38 n-groups), 1 CTA/SM, 256 threads.
// smem: A tile [34816B] | B stage0 [34816B] | B stage1 [34816B]
extern __shared__ __align__(16) unsigned char dynraw[];

__global__ void __launch_bounds__(256, 1)
gemm_kernel(const float* __restrict__ out_bias, float* __restrict__ out) {
    __shared__ float sBias[128];
    __shared__ float sRm[128][2];
    __shared__ float sRs[128][2];

    const int tid  = threadIdx.x;
    const int warp = tid >> 5, lane = tid & 31;
    const int wm   = warp & 3;          // warp m index (4)
    const int wn   = warp >> 2;         // warp n index (2)
    const int m0   = (blockIdx.x & 3) * 128;
    const int grp  = blockIdx.x >> 2;   // 0..37

    const unsigned aBase  = sptr(dynraw);
    const unsigned bBase0 = aBase + TILEB;
    const unsigned bBase1 = aBase + 2 * TILEB;

    // ---- load A tile once: 128 rows x 16 segs of 16B --------------------------
    #pragma unroll
    for (int i = 0; i < 8; i++) {
        int lin = tid + i * 256;
        int r = lin >> 4, s = lin & 15;
        cp_async16(aBase + (unsigned)(r * 272 + s * 16),
                   &g_uh[(m0 + r) * DIM + s * 8], 16);
    }

    auto load_B = [&](int n, unsigned bb) {
        #pragma unroll
        for (int i = 0; i < 8; i++) {
            int lin = tid + i * 256;
            int r = lin >> 4, s = lin & 15;
            int g  = n * 128 + r;
            int gc = g < N_ENT ? g : 0;
            cp_async16(bb + (unsigned)(r * 272 + s * 16),
                       &g_eh[(size_t)gc * DIM + s * 8], g < N_ENT ? 16 : 0);
        }
    };

    load_B(grp, bBase0);
    cp_commit();                         // group: A + B(tile0)
    cp_wait<0>();
    __syncthreads();

    // ---- hoist A fragments into registers (fixed for all n-tiles) ----------
    unsigned aF[8][2][4];
    {
        const unsigned* sA = (const unsigned*)dynraw;
        const int ar = wm * 32 + (lane >> 2);
        #pragma unroll
        for (int ks = 0; ks < 8; ks++) {
            const int kp = ks * 8 + (lane & 3);    // half-pair index along k
            #pragma unroll
            for (int mf = 0; mf < 2; mf++) {
                int r = ar + mf * 16;
                aF[ks][mf][0] = sA[r * RSW + kp];
                aF[ks][mf][1] = sA[(r + 8) * RSW + kp];
                aF[ks][mf][2] = sA[r * RSW + kp + 4];
                aF[ks][mf][3] = sA[(r + 8) * RSW + kp + 4];
            }
        }
    }

    int it = 0;
    for (int n = grp; n < NTILE; n += NGRP, it++) {
        const unsigned curB = (it & 1) ? bBase1 : bBase0;
        const unsigned nxtB = (it & 1) ? bBase0 : bBase1;
        const bool have_next = (n + NGRP) < NTILE;

        if (have_next) { load_B(n + NGRP, nxtB); cp_commit(); cp_wait<1>(); }
        else           { cp_wait<0>(); }
        __syncthreads();                 // current B resident

        if (tid < 128) {
            int g = n * 128 + tid;
            sBias[tid] = (g < N_ENT) ? out_bias[g] : 0.f;
        }

        // ---- mainloop: full K, no syncs ------------------------------------
        float acc[2][8][4];
        #pragma unroll
        for (int i = 0; i < 2; i++)
            #pragma unroll
            for (int j = 0; j < 8; j++)
                #pragma unroll
                for (int k = 0; k < 4; k++) acc[i][j][k] = 0.f;

        const unsigned* sB = (const unsigned*)(dynraw + (curB - aBase));
        #pragma unroll
        for (int ks = 0; ks < 8; ks++) {
            const int kp = ks * 8 + (lane & 3);
            #pragma unroll
            for (int nf = 0; nf < 8; nf++) {
                int br = wn * 64 + nf * 8 + (lane >> 2);
                unsigned b0 = sB[br * RSW + kp];
                unsigned b1 = sB[br * RSW + kp + 4];
                mma_f16(acc[0][nf], aF[ks][0], b0, b1);
                mma_f16(acc[1][nf], aF[ks][1], b0, b1);
            }
        }
        __syncthreads();                 // sBias visible; mainloop done

        // ---- epilogue: bias, store, streaming (max, sumexp) ----------------
        const float NEG = -1e30f;
        #pragma unroll
        for (int mf = 0; mf < 2; mf++) {
            #pragma unroll
            for (int h = 0; h < 2; h++) {
                const int rl = wm * 32 + mf * 16 + h * 8 + (lane >> 2);
                const size_t grow = (size_t)(m0 + rl) * N_ENT;
                float mx = NEG;
                #pragma unroll
                for (int nf = 0; nf < 8; nf++) {
                    int c = wn * 64 + nf * 8 + ((lane & 3) << 1);
                    int g = n * 128 + c;
                    float v0 = acc[mf][nf][2 * h]     + sBias[c];
                    float v1 = acc[mf][nf][2 * h + 1] + sBias[c + 1];
                    if (g + 1 < N_ENT) {
                        *(float2*)&out[grow + g] = make_float2(v0, v1);
                    } else if (g < N_ENT) {
                        out[grow + g] = v0;
                        v1 = NEG;
                    } else {
                        v0 = NEG; v1 = NEG;
                    }
                    acc[mf][nf][2 * h]     = v0;
                    acc[mf][nf][2 * h + 1] = v1;
                    mx = fmaxf(mx, fmaxf(v0, v1));
                }
                float s = 0.f;
                #pragma unroll
                for (int nf = 0; nf < 8; nf++)
                    s += __expf(acc[mf][nf][2 * h] - mx)
                       + __expf(acc[mf][nf][2 * h + 1] - mx);
                #pragma unroll
                for (int off = 1; off <= 2; off <<= 1) {
                    float om = __shfl_xor_sync(0xffffffffu, mx, off);
                    float os = __shfl_xor_sync(0xffffffffu, s,  off);
                    float nm = fmaxf(mx, om);
                    s = s * __expf(mx - nm) + os * __expf(om - nm);
                    mx = nm;
                }
                if ((lane & 3) == 0) {
                    sRm[rl][wn] = mx;
                    sRs[rl][wn] = s;
                }
            }
        }
        __syncthreads();
        if (tid < 128) {
            float ma = sRm[tid][0], mb = sRm[tid][1];
            float sa = sRs[tid][0], sb = sRs[tid][1];
            float nm = fmaxf(ma, mb);
            float ss = sa * __expf(ma - nm) + sb * __expf(mb - nm);
            g_pms[(m0 + tid) * NTP + n] = make_float2(nm, ss);
        }
        __syncthreads();                 // protect sRm/sRs reuse
    }
}

// ---------------- kernel 4: per-row logsumexp + picked (4-stream MLP) --------
__global__ void lse_kernel(const float* __restrict__ out,
                           const int* __restrict__ labels) {
    int w = threadIdx.x >> 5, lane = threadIdx.x & 31;
    int b = blockIdx.x * 8 + w;        // grid 64 x 256 -> 512 rows
    float mx0 = -1e30f, mx1 = -1e30f, mx2 = -1e30f, mx3 = -1e30f;
    float s0 = 0.f, s1 = 0.f, s2 = 0.f, s3 = 0.f;
    for (int t0 = 0; t0 < NTILE; t0 += 128) {
        int t = t0 + lane;
        if (t < NTILE) {
            float2 p = g_pms[b * NTP + t];
            float nm = fmaxf(mx0, p.x);
            s0 = s0 * __expf(mx0 - nm) + p.y * __expf(p.x - nm); mx0 = nm;
        }
        if (t + 32 < NTILE) {
            float2 p = g_pms[b * NTP + t + 32];
            float nm = fmaxf(mx1, p.x);
            s1 = s1 * __expf(mx1 - nm) + p.y * __expf(p.x - nm); mx1 = nm;
        }
        if (t + 64 < NTILE) {
            float2 p = g_pms[b * NTP + t + 64];
            float nm = fmaxf(mx2, p.x);
            s2 = s2 * __expf(mx2 - nm) + p.y * __expf(p.x - nm); mx2 = nm;
        }
        if (t + 96 < NTILE) {
            float2 p = g_pms[b * NTP + t + 96];
            float nm = fmaxf(mx3, p.x);
            s3 = s3 * __expf(mx3 - nm) + p.y * __expf(p.x - nm); mx3 = nm;
        }
    }
    float nm01 = fmaxf(mx0, mx1);
    float s01  = s0 * __expf(mx0 - nm01) + s1 * __expf(mx1 - nm01);
    float nm23 = fmaxf(mx2, mx3);
    float s23  = s2 * __expf(mx2 - nm23) + s3 * __expf(mx3 - nm23);
    float mx   = fmaxf(nm01, nm23);
    float s    = s01 * __expf(nm01 - mx) + s23 * __expf(nm23 - mx);
    #pragma unroll
    for (int o = 16; o; o >>= 1) {
        float om = __shfl_xor_sync(0xffffffffu, mx, o);
        float os = __shfl_xor_sync(0xffffffffu, s,  o);
        float nm = fmaxf(mx, om);
        s = s * __expf(mx - nm) + os * __expf(om - nm);
        mx = nm;
    }
    if (lane == 0) {
        float logz = mx + logf(s);
        g_lp[b] = logz - out[(size_t)b * N_ENT + labels[b]];
    }
}

// ---------------- kernel 5: mean loss -> tail of d_out ------------------------
__global__ void loss_kernel(float* __restrict__ out, int out_size) {
    int tid = threadIdx.x;             // 512
    __shared__ float red[BATCH];
    red[tid] = g_lp[tid];
    __syncthreads();
    for (int o = 256; o; o >>= 1) {
        if (tid < o) red[tid] += red[tid + o];
        __syncthreads();
    }
    __shared__ float loss_s;
    if (tid == 0) loss_s = red[0] / (float)BATCH;
    __syncthreads();
    const long base = (long)BATCH * N_ENT;
    for (long i = base + tid; i < (long)out_size; i += 512)
        out[i] = loss_s;
}

// ---------------- launch ------------------------------------------------------
extern "C" void kernel_launch(void* const* d_in, const int* in_sizes, int n_in,
                              void* d_out, int out_size) {
    const float* entity_emb = (const float*)d_in[0];
    const float* W1         = (const float*)d_in[1];
    const float* W2         = (const float*)d_in[2];
    const float* q          = (const float*)d_in[3];
    const float* soft_bias  = (const float*)d_in[4];
    const float* out_bias   = (const float*)d_in[5];
    const int*   seed_sets  = (const int*)d_in[6];   // jax default: int64 -> int32
    const int*   labels     = (const int*)d_in[7];
    float* out = (float*)d_out;

    const int dyn_bytes = 3 * TILEB;                 // 104,448 B
    cudaFuncSetAttribute(gemm_kernel,
                         cudaFuncAttributeMaxDynamicSharedMemorySize, dyn_bytes);

    econv_kernel<<<N_ENT * DIM / (256 * 8), 256>>>(entity_emb);
    prep_kernel<<<1, 128>>>(W1, W2, q, soft_bias);
    uemb_kernel<<<BATCH, 128>>>(entity_emb, seed_sets);
    gemm_kernel<<<4 * NGRP, 256, dyn_bytes>>>(out_bias, out);
    lse_kernel<<<64, 256>>>(out, labels);
    loss_kernel<<<1, BATCH>>>(out, out_size);
}

// round 9
// speedup vs baseline: 1.4070x; 1.0132x over previous
#include <cuda_runtime.h>
#include <cuda_fp16.h>
#include <math.h>

#define N_ENT   64368
#define DIM     128
#define BATCH   512
#define SEQ     50
#define NTILE   503          // ceil(64368/128)
#define NTP     512          // padded partial stride
#define NGRP    38           // n-groups; grid = 4*38 = 152 persistent CTAs
#define RSW     68           // words per smem row (272B, conflict-free frags)
#define TILEB   (128 * 272)  // bytes per 128x128 half tile (34816)

// ---------------- scratch (device globals; no allocations allowed) ----------
__device__ float g_r1[DIM];
__device__ float g_r2[DIM];
__device__ float g_c;
__device__ __align__(16) __half g_uh[BATCH * DIM];
__device__ __align__(16) __half g_eh[N_ENT * DIM];     // fp16 entity_emb (16.5MB)
__device__ __align__(16) float2 g_pms[BATCH * NTP];
__device__ float g_lp[BATCH];

// ---------------- helpers ----------------------------------------------------
__device__ __forceinline__ unsigned sptr(const void* p) {
    return (unsigned)__cvta_generic_to_shared(p);
}
__device__ __forceinline__ void cp_async16(unsigned dst, const void* src, int sz) {
    asm volatile("cp.async.cg.shared.global [%0], [%1], 16, %2;\n"
                 :: "r"(dst), "l"(src), "r"(sz));
}
__device__ __forceinline__ void cp_commit() { asm volatile("cp.async.commit_group;\n"); }
template <int N> __device__ __forceinline__ void cp_wait() {
    asm volatile("cp.async.wait_group %0;\n" :: "n"(N));
}
__device__ __forceinline__ void mma_f16(float* d, const unsigned* a, unsigned b0, unsigned b1) {
    asm volatile(
        "mma.sync.aligned.m16n8k16.row.col.f32.f16.f16.f32 "
        "{%0,%1,%2,%3}, {%4,%5,%6,%7}, {%8,%9}, {%0,%1,%2,%3};\n"
        : "+f"(d[0]), "+f"(d[1]), "+f"(d[2]), "+f"(d[3])
        : "r"(a[0]), "r"(a[1]), "r"(a[2]), "r"(a[3]), "r"(b0), "r"(b1));
}

// ---------------- kernel 0: entity_emb f32 -> f16 ----------------------------
__global__ void econv_kernel(const float* __restrict__ emb) {
    size_t base = ((size_t)blockIdx.x * blockDim.x + threadIdx.x) * 8;
    float4 a = *(const float4*)&emb[base];
    float4 b = *(const float4*)&emb[base + 4];
    __half2 h[4];
    h[0] = __floats2half2_rn(a.x, a.y);
    h[1] = __floats2half2_rn(a.z, a.w);
    h[2] = __floats2half2_rn(b.x, b.y);
    h[3] = __floats2half2_rn(b.z, b.w);
    *(uint4*)&g_eh[base] = *(uint4*)h;
}

// ---------------- kernel 1: r1 = W1^T q, r2 = W2^T q, c = soft_bias * sum(q) -
__global__ void prep_kernel(const float* __restrict__ W1, const float* __restrict__ W2,
                            const float* __restrict__ q,  const float* __restrict__ soft_bias) {
    int d = threadIdx.x;               // 128 threads
    __shared__ float sq[DIM];
    __shared__ float red[DIM];
    sq[d] = q[d];
    __syncthreads();
    float r1 = 0.f, r2 = 0.f;
    #pragma unroll 8
    for (int e = 0; e < DIM; e++) {
        float qe = sq[e];
        r1 += qe * W1[e * DIM + d];
        r2 += qe * W2[e * DIM + d];
    }
    g_r1[d] = r1;
    g_r2[d] = r2;
    red[d] = sq[d];
    __syncthreads();
    for (int s = 64; s > 0; s >>= 1) {
        if (d < s) red[d] += red[d + s];
        __syncthreads();
    }
    if (d == 0) g_c = soft_bias[0] * red[0];
}

// ---------------- kernel 2: u_emb, 2D block (128 dims x 8 rows parallel) -----
__global__ void __launch_bounds__(1024)
uemb_kernel(const float* __restrict__ emb, const int* __restrict__ seeds) {
    int b  = blockIdx.x;
    int tx = threadIdx.x;              // dim 0..127
    int ty = threadIdx.y;              // row stride 0..7
    int tid = ty * 128 + tx;
    int warp = tid >> 5, lane = tid & 31;

    __shared__ float v[SEQ][DIM];
    __shared__ float att[SEQ];
    __shared__ float sr1[DIM], sr2[DIM];
    __shared__ float dn;
    __shared__ float part[8][DIM];

    if (ty == 0) { sr1[tx] = g_r1[tx]; sr2[tx] = g_r2[tx]; }

    float w = expf(-(float)(tx & ~1) * (logf(10000.0f) / (float)DIM));
    bool odd = (tx & 1);

    // gather 8 rows in parallel -> 7 dependent rounds instead of 50
    for (int l = ty; l < SEQ; l += 8) {
        int idx = seeds[b * SEQ + l];
        float arg = (float)l * w;
        float pe = (odd ? cosf(arg) : sinf(arg)) * 0.001f;
        v[l][tx] = emb[(size_t)idx * DIM + tx] + pe;
    }
    __syncthreads();

    // att_raw[l] = r1 . v[l] : one warp per l (32 warps cover 50 in 2 rounds)
    for (int l = warp; l < SEQ; l += 32) {
        float p = sr1[lane]      * v[l][lane]
                + sr1[lane + 32] * v[l][lane + 32]
                + sr1[lane + 64] * v[l][lane + 64]
                + sr1[lane + 96] * v[l][lane + 96];
        #pragma unroll
        for (int o = 16; o; o >>= 1) p += __shfl_xor_sync(0xffffffffu, p, o);
        if (lane == 0) att[l] = p;
    }
    if (warp == 0) {
        float p = sr2[lane]      * v[SEQ - 1][lane]
                + sr2[lane + 32] * v[SEQ - 1][lane + 32]
                + sr2[lane + 64] * v[SEQ - 1][lane + 64]
                + sr2[lane + 96] * v[SEQ - 1][lane + 96];
        #pragma unroll
        for (int o = 16; o; o >>= 1) p += __shfl_xor_sync(0xffffffffu, p, o);
        if (lane == 0) dn = p + g_c;
    }
    __syncthreads();
    if (tid < SEQ) att[tid] += dn;
    __syncthreads();

    // u[d] = sum_l att[l] v[l][d] : 8-way partial then tree
    float pacc = 0.f;
    for (int l = ty; l < SEQ; l += 8) pacc += att[l] * v[l][tx];
    part[ty][tx] = pacc;
    __syncthreads();
    if (ty < 4) part[ty][tx] += part[ty + 4][tx];
    __syncthreads();
    if (ty < 2) part[ty][tx] += part[ty + 2][tx];
    __syncthreads();
    if (ty == 0)
        g_uh[b * DIM + tx] = __float2half_rn(part[0][tx] + part[1][tx]);
}

// ---------------- kernel 3: persistent fp16 mma GEMM + fused streaming LSE ---
// grid = 152 (4 m-tiles x 38 n-groups), 1 CTA/SM, 512 threads (16 warps).
// warp grid 8(m) x 2(n): warp tile 16x64.
extern __shared__ __align__(16) unsigned char dynraw[];

__global__ void __launch_bounds__(512, 1)
gemm_kernel(const float* __restrict__ out_bias, float* __restrict__ out) {
    __shared__ float sBias[128];
    __shared__ float sRm[128][2];
    __shared__ float sRs[128][2];

    const int tid  = threadIdx.x;
    const int warp = tid >> 5, lane = tid & 31;
    const int wm   = warp & 7;          // warp m index (8)
    const int wn   = warp >> 3;         // warp n index (2)
    const int m0   = (blockIdx.x & 3) * 128;
    const int grp  = blockIdx.x >> 2;   // 0..37

    const unsigned aBase  = sptr(dynraw);
    const unsigned bBase0 = aBase + TILEB;
    const unsigned bBase1 = aBase + 2 * TILEB;

    // ---- load A tile once: 128 rows x 16 segs of 16B -----------------------
    #pragma unroll
    for (int i = 0; i < 4; i++) {
        int lin = tid + i * 512;
        int r = lin >> 4, s = lin & 15;
        cp_async16(aBase + (unsigned)(r * 272 + s * 16),
                   &g_uh[(m0 + r) * DIM + s * 8], 16);
    }

    auto load_B = [&](int n, unsigned bb) {
        #pragma unroll
        for (int i = 0; i < 4; i++) {
            int lin = tid + i * 512;
            int r = lin >> 4, s = lin & 15;
            int g  = n * 128 + r;
            int gc = g < N_ENT ? g : 0;
            cp_async16(bb + (unsigned)(r * 272 + s * 16),
                       &g_eh[(size_t)gc * DIM + s * 8], g < N_ENT ? 16 : 0);
        }
    };

    load_B(grp, bBase0);
    cp_commit();                         // group: A + B(tile0)
    cp_wait<0>();
    __syncthreads();

    // ---- hoist A fragments (warp tile 16 rows) into registers --------------
    unsigned aF[8][4];
    {
        const unsigned* sA = (const unsigned*)dynraw;
        const int ar = wm * 16 + (lane >> 2);
        #pragma unroll
        for (int ks = 0; ks < 8; ks++) {
            const int kp = ks * 8 + (lane & 3);
            aF[ks][0] = sA[ar * RSW + kp];
            aF[ks][1] = sA[(ar + 8) * RSW + kp];
            aF[ks][2] = sA[ar * RSW + kp + 4];
            aF[ks][3] = sA[(ar + 8) * RSW + kp + 4];
        }
    }

    int it = 0;
    for (int n = grp; n < NTILE; n += NGRP, it++) {
        const unsigned curB = (it & 1) ? bBase1 : bBase0;
        const unsigned nxtB = (it & 1) ? bBase0 : bBase1;
        const bool have_next = (n + NGRP) < NTILE;

        if (have_next) { load_B(n + NGRP, nxtB); cp_commit(); cp_wait<1>(); }
        else           { cp_wait<0>(); }
        __syncthreads();                 // current B resident

        if (tid < 128) {
            int g = n * 128 + tid;
            sBias[tid] = (g < N_ENT) ? out_bias[g] : 0.f;
        }

        // ---- mainloop: full K, no syncs ------------------------------------
        float acc[8][4];
        #pragma unroll
        for (int j = 0; j < 8; j++)
            #pragma unroll
            for (int k = 0; k < 4; k++) acc[j][k] = 0.f;

        const unsigned* sB = (const unsigned*)(dynraw + (curB - aBase));
        #pragma unroll
        for (int ks = 0; ks < 8; ks++) {
            const int kp = ks * 8 + (lane & 3);
            #pragma unroll
            for (int nf = 0; nf < 8; nf++) {
                int br = wn * 64 + nf * 8 + (lane >> 2);
                unsigned b0 = sB[br * RSW + kp];
                unsigned b1 = sB[br * RSW + kp + 4];
                mma_f16(acc[nf], aF[ks], b0, b1);
            }
        }
        __syncthreads();                 // sBias visible; mainloop done

        // ---- epilogue: bias, store, streaming (max, sumexp) ----------------
        const float NEG = -1e30f;
        #pragma unroll
        for (int h = 0; h < 2; h++) {
            const int rl = wm * 16 + h * 8 + (lane >> 2);
            const size_t grow = (size_t)(m0 + rl) * N_ENT;
            float mx = NEG;
            #pragma unroll
            for (int nf = 0; nf < 8; nf++) {
                int c = wn * 64 + nf * 8 + ((lane & 3) << 1);
                int g = n * 128 + c;
                float v0 = acc[nf][2 * h]     + sBias[c];
                float v1 = acc[nf][2 * h + 1] + sBias[c + 1];
                if (g + 1 < N_ENT) {
                    *(float2*)&out[grow + g] = make_float2(v0, v1);
                } else if (g < N_ENT) {
                    out[grow + g] = v0;
                    v1 = NEG;
                } else {
                    v0 = NEG; v1 = NEG;
                }
                acc[nf][2 * h]     = v0;
                acc[nf][2 * h + 1] = v1;
                mx = fmaxf(mx, fmaxf(v0, v1));
            }
            float s = 0.f;
            #pragma unroll
            for (int nf = 0; nf < 8; nf++)
                s += __expf(acc[nf][2 * h] - mx) + __expf(acc[nf][2 * h + 1] - mx);
            #pragma unroll
            for (int off = 1; off <= 2; off <<= 1) {
                float om = __shfl_xor_sync(0xffffffffu, mx, off);
                float os = __shfl_xor_sync(0xffffffffu, s,  off);
                float nm = fmaxf(mx, om);
                s = s * __expf(mx - nm) + os * __expf(om - nm);
                mx = nm;
            }
            if ((lane & 3) == 0) {
                sRm[rl][wn] = mx;
                sRs[rl][wn] = s;
            }
        }
        __syncthreads();
        if (tid < 128) {
            float ma = sRm[tid][0], mb = sRm[tid][1];
            float sa = sRs[tid][0], sb = sRs[tid][1];
            float nm = fmaxf(ma, mb);
            float ss = sa * __expf(ma - nm) + sb * __expf(mb - nm);
            g_pms[(m0 + tid) * NTP + n] = make_float2(nm, ss);
        }
        __syncthreads();                 // protect sRm/sRs reuse
    }
}

// ---------------- kernel 4: per-row logsumexp + picked (4-stream MLP) --------
__global__ void lse_kernel(const float* __restrict__ out,
                           const int* __restrict__ labels) {
    int w = threadIdx.x >> 5, lane = threadIdx.x & 31;
    int b = blockIdx.x * 8 + w;        // grid 64 x 256 -> 512 rows
    float mx0 = -1e30f, mx1 = -1e30f, mx2 = -1e30f, mx3 = -1e30f;
    float s0 = 0.f, s1 = 0.f, s2 = 0.f, s3 = 0.f;
    for (int t0 = 0; t0 < NTILE; t0 += 128) {
        int t = t0 + lane;
        if (t < NTILE) {
            float2 p = g_pms[b * NTP + t];
            float nm = fmaxf(mx0, p.x);
            s0 = s0 * __expf(mx0 - nm) + p.y * __expf(p.x - nm); mx0 = nm;
        }
        if (t + 32 < NTILE) {
            float2 p = g_pms[b * NTP + t + 32];
            float nm = fmaxf(mx1, p.x);
            s1 = s1 * __expf(mx1 - nm) + p.y * __expf(p.x - nm); mx1 = nm;
        }
        if (t + 64 < NTILE) {
            float2 p = g_pms[b * NTP + t + 64];
            float nm = fmaxf(mx2, p.x);
            s2 = s2 * __expf(mx2 - nm) + p.y * __expf(p.x - nm); mx2 = nm;
        }
        if (t + 96 < NTILE) {
            float2 p = g_pms[b * NTP + t + 96];
            float nm = fmaxf(mx3, p.x);
            s3 = s3 * __expf(mx3 - nm) + p.y * __expf(p.x - nm); mx3 = nm;
        }
    }
    float nm01 = fmaxf(mx0, mx1);
    float s01  = s0 * __expf(mx0 - nm01) + s1 * __expf(mx1 - nm01);
    float nm23 = fmaxf(mx2, mx3);
    float s23  = s2 * __expf(mx2 - nm23) + s3 * __expf(mx3 - nm23);
    float mx   = fmaxf(nm01, nm23);
    float s    = s01 * __expf(nm01 - mx) + s23 * __expf(nm23 - mx);
    #pragma unroll
    for (int o = 16; o; o >>= 1) {
        float om = __shfl_xor_sync(0xffffffffu, mx, o);
        float os = __shfl_xor_sync(0xffffffffu, s,  o);
        float nm = fmaxf(mx, om);
        s = s * __expf(mx - nm) + os * __expf(om - nm);
        mx = nm;
    }
    if (lane == 0) {
        float logz = mx + logf(s);
        g_lp[b] = logz - out[(size_t)b * N_ENT + labels[b]];
    }
}

// ---------------- kernel 5: mean loss -> tail of d_out ------------------------
__global__ void loss_kernel(float* __restrict__ out, int out_size) {
    int tid = threadIdx.x;             // 512
    __shared__ float red[BATCH];
    red[tid] = g_lp[tid];
    __syncthreads();
    for (int o = 256; o; o >>= 1) {
        if (tid < o) red[tid] += red[tid + o];
        __syncthreads();
    }
    __shared__ float loss_s;
    if (tid == 0) loss_s = red[0] / (float)BATCH;
    __syncthreads();
    const long base = (long)BATCH * N_ENT;
    for (long i = base + tid; i < (long)out_size; i += 512)
        out[i] = loss_s;
}

// ---------------- launch ------------------------------------------------------
extern "C" void kernel_launch(void* const* d_in, const int* in_sizes, int n_in,
                              void* d_out, int out_size) {
    const float* entity_emb = (const float*)d_in[0];
    const float* W1         = (const float*)d_in[1];
    const float* W2         = (const float*)d_in[2];
    const float* q          = (const float*)d_in[3];
    const float* soft_bias  = (const float*)d_in[4];
    const float* out_bias   = (const float*)d_in[5];
    const int*   seed_sets  = (const int*)d_in[6];   // jax default: int64 -> int32
    const int*   labels     = (const int*)d_in[7];
    float* out = (float*)d_out;

    const int dyn_bytes = 3 * TILEB;                 // 104,448 B
    cudaFuncSetAttribute(gemm_kernel,
                         cudaFuncAttributeMaxDynamicSharedMemorySize, dyn_bytes);

    econv_kernel<<<N_ENT * DIM / (256 * 8), 256>>>(entity_emb);
    prep_kernel<<<1, 128>>>(W1, W2, q, soft_bias);
    uemb_kernel<<<BATCH, dim3(128, 8)>>>(entity_emb, seed_sets);
    gemm_kernel<<<4 * NGRP, 512, dyn_bytes>>>(out_bias, out);
    lse_kernel<<<64, 256>>>(out, labels);
    loss_kernel<<<1, BATCH>>>(out, out_size);
}

// round 10
// speedup vs baseline: 1.9136x; 1.3600x over previous
#include <cuda_runtime.h>
#include <cuda_fp16.h>
#include <math.h>

#define N_ENT   64368
#define DIM     128
#define BATCH   512
#define SEQ     50
#define BN      64           // gemm n-tile width
#define NT2     1006         // ceil(64368/64)
#define NTP     1024         // padded partial stride
#define NGRP2   76           // n-groups; grid = 4*76 = 304 (2 CTAs/SM)
#define RSW     68           // words per smem row (272B)
#define ABYTES  (128 * 272)  // A tile bytes (34816)
#define BBYTES  (64 * 272)   // B tile bytes (17408)

// ---------------- scratch (device globals; no allocations allowed) ----------
__device__ float g_p1[16 * DIM];
__device__ float g_p2[16 * DIM];
__device__ float g_pe[SEQ * DIM];
__device__ float g_c;
__device__ __align__(16) __half g_uh[BATCH * DIM];
__device__ __align__(16) __half g_eh[N_ENT * DIM];     // fp16 entity_emb
__device__ __align__(16) float2 g_pms[BATCH * NTP];
__device__ float g_lp[BATCH];

// ---------------- helpers ----------------------------------------------------
__device__ __forceinline__ unsigned sptr(const void* p) {
    return (unsigned)__cvta_generic_to_shared(p);
}
__device__ __forceinline__ void cp_async16(unsigned dst, const void* src, int sz) {
    asm volatile("cp.async.cg.shared.global [%0], [%1], 16, %2;\n"
                 :: "r"(dst), "l"(src), "r"(sz));
}
__device__ __forceinline__ void cp_commit() { asm volatile("cp.async.commit_group;\n"); }
template <int N> __device__ __forceinline__ void cp_wait() {
    asm volatile("cp.async.wait_group %0;\n" :: "n"(N));
}
__device__ __forceinline__ void mma_f16(float* d, const unsigned* a, unsigned b0, unsigned b1) {
    asm volatile(
        "mma.sync.aligned.m16n8k16.row.col.f32.f16.f16.f32 "
        "{%0,%1,%2,%3}, {%4,%5,%6,%7}, {%8,%9}, {%0,%1,%2,%3};\n"
        : "+f"(d[0]), "+f"(d[1]), "+f"(d[2]), "+f"(d[3])
        : "r"(a[0]), "r"(a[1]), "r"(a[2]), "r"(a[3]), "r"(b0), "r"(b1));
}

// ---------------- K1: econv (0..4022) | W-partials (4023..4038) | PE (4039..4088)
__global__ void k1_kernel(const float* __restrict__ emb,
                          const float* __restrict__ W1, const float* __restrict__ W2,
                          const float* __restrict__ q,  const float* __restrict__ soft_bias) {
    const int bid = blockIdx.x;
    const int tid = threadIdx.x;

    if (bid < 4023) {
        // entity_emb f32 -> f16, 8 elems/thread
        size_t base = ((size_t)bid * 256 + tid) * 8;
        float4 a = *(const float4*)&emb[base];
        float4 b = *(const float4*)&emb[base + 4];
        __half2 h[4];
        h[0] = __floats2half2_rn(a.x, a.y);
        h[1] = __floats2half2_rn(a.z, a.w);
        h[2] = __floats2half2_rn(b.x, b.y);
        h[3] = __floats2half2_rn(b.z, b.w);
        *(uint4*)&g_eh[base] = *(uint4*)h;
    } else if (bid < 4039) {
        // partial r1/r2: block p covers 8 rows of W
        int p = bid - 4023;
        if (tid < 128) {
            float s1 = 0.f, s2 = 0.f;
            #pragma unroll
            for (int e = 0; e < 8; e++) {
                int er = p * 8 + e;
                float qe = q[er];
                s1 += qe * W1[er * DIM + tid];
                s2 += qe * W2[er * DIM + tid];
            }
            g_p1[p * DIM + tid] = s1;
            g_p2[p * DIM + tid] = s2;
        }
    } else {
        // positional-encoding row l
        int l = bid - 4039;
        if (tid < 128) {
            float w = expf(-(float)(tid & ~1) * (logf(10000.0f) / (float)DIM));
            float arg = (float)l * w;
            g_pe[l * DIM + tid] = ((tid & 1) ? cosf(arg) : sinf(arg)) * 0.001f;
        }
        if (l == 0) {      // also compute c = soft_bias * sum(q)
            __shared__ float rq[128];
            if (tid < 128) rq[tid] = q[tid];
            __syncthreads();
            for (int o = 64; o; o >>= 1) {
                if (tid < o) rq[tid] += rq[tid + o];
                __syncthreads();
            }
            if (tid == 0) g_c = soft_bias[0] * rq[0];
        }
    }
}

// ---------------- K2: u_emb (2D block, PE table, inline r-reduction) ---------
__global__ void __launch_bounds__(1024)
uemb_kernel(const float* __restrict__ emb, const int* __restrict__ seeds) {
    int b  = blockIdx.x;
    int tx = threadIdx.x;              // dim 0..127
    int ty = threadIdx.y;              // 0..7
    int tid = ty * 128 + tx;
    int warp = tid >> 5, lane = tid & 31;

    __shared__ float v[SEQ][DIM];
    __shared__ float att[SEQ];
    __shared__ float sr1[DIM], sr2[DIM];
    __shared__ float dn;
    __shared__ float part[8][DIM];

    if (ty == 0) {
        float s = 0.f;
        #pragma unroll
        for (int p = 0; p < 16; p++) s += g_p1[p * DIM + tx];
        sr1[tx] = s;
    } else if (ty == 1) {
        float s = 0.f;
        #pragma unroll
        for (int p = 0; p < 16; p++) s += g_p2[p * DIM + tx];
        sr2[tx] = s;
    }

    // gather 8 rows in parallel
    for (int l = ty; l < SEQ; l += 8) {
        int idx = seeds[b * SEQ + l];
        v[l][tx] = emb[(size_t)idx * DIM + tx] + g_pe[l * DIM + tx];
    }
    __syncthreads();

    for (int l = warp; l < SEQ; l += 32) {
        float p = sr1[lane]      * v[l][lane]
                + sr1[lane + 32] * v[l][lane + 32]
                + sr1[lane + 64] * v[l][lane + 64]
                + sr1[lane + 96] * v[l][lane + 96];
        #pragma unroll
        for (int o = 16; o; o >>= 1) p += __shfl_xor_sync(0xffffffffu, p, o);
        if (lane == 0) att[l] = p;
    }
    if (warp == 0) {
        float p = sr2[lane]      * v[SEQ - 1][lane]
                + sr2[lane + 32] * v[SEQ - 1][lane + 32]
                + sr2[lane + 64] * v[SEQ - 1][lane + 64]
                + sr2[lane + 96] * v[SEQ - 1][lane + 96];
        #pragma unroll
        for (int o = 16; o; o >>= 1) p += __shfl_xor_sync(0xffffffffu, p, o);
        if (lane == 0) dn = p + g_c;
    }
    __syncthreads();
    if (tid < SEQ) att[tid] += dn;
    __syncthreads();

    float pacc = 0.f;
    for (int l = ty; l < SEQ; l += 8) pacc += att[l] * v[l][tx];
    part[ty][tx] = pacc;
    __syncthreads();
    if (ty < 4) part[ty][tx] += part[ty + 4][tx];
    __syncthreads();
    if (ty < 2) part[ty][tx] += part[ty + 2][tx];
    __syncthreads();
    if (ty == 0)
        g_uh[b * DIM + tx] = __float2half_rn(part[0][tx] + part[1][tx]);
}

// ---------------- K3: persistent fp16 GEMM (2 CTAs/SM) + fused streaming LSE -
// grid = 304 (4 m-tiles x 76 n-groups), 256 threads, tile 128m x 64n.
// smem: A [34816] | B stage0 [17408] | B stage1 [17408] = 69632 B
extern __shared__ __align__(16) unsigned char dynraw[];

__global__ void __launch_bounds__(256, 2)
gemm_kernel(const float* __restrict__ out_bias, float* __restrict__ out) {
    __shared__ float sBias[BN];
    __shared__ float sRm[128][2];
    __shared__ float sRs[128][2];

    const int tid  = threadIdx.x;
    const int warp = tid >> 5, lane = tid & 31;
    const int wm   = warp & 3;          // warp m index (4)
    const int wn   = warp >> 2;         // warp n index (2) -> 32-col halves
    const int m0   = (blockIdx.x & 3) * 128;
    const int grp  = blockIdx.x >> 2;   // 0..75

    const unsigned aBase  = sptr(dynraw);
    const unsigned bBase0 = aBase + ABYTES;
    const unsigned bBase1 = bBase0 + BBYTES;

    // ---- load A tile once: 128 rows x 16 segs of 16B -----------------------
    #pragma unroll
    for (int i = 0; i < 8; i++) {
        int lin = tid + i * 256;
        int r = lin >> 4, s = lin & 15;
        cp_async16(aBase + (unsigned)(r * 272 + s * 16),
                   &g_uh[(m0 + r) * DIM + s * 8], 16);
    }

    auto load_B = [&](int nt, unsigned bb) {
        #pragma unroll
        for (int i = 0; i < 4; i++) {
            int lin = tid + i * 256;
            int r = lin >> 4, s = lin & 15;   // r 0..63
            int g  = nt * BN + r;
            int gc = g < N_ENT ? g : 0;
            cp_async16(bb + (unsigned)(r * 272 + s * 16),
                       &g_eh[(size_t)gc * DIM + s * 8], g < N_ENT ? 16 : 0);
        }
    };

    load_B(grp, bBase0);
    cp_commit();                         // group: A + B(tile0)
    cp_wait<0>();
    __syncthreads();

    // ---- hoist A fragments (32 m-rows per warp) into registers -------------
    unsigned aF[8][2][4];
    {
        const unsigned* sA = (const unsigned*)dynraw;
        const int ar = wm * 32 + (lane >> 2);
        #pragma unroll
        for (int ks = 0; ks < 8; ks++) {
            const int kp = ks * 8 + (lane & 3);
            #pragma unroll
            for (int mf = 0; mf < 2; mf++) {
                int r = ar + mf * 16;
                aF[ks][mf][0] = sA[r * RSW + kp];
                aF[ks][mf][1] = sA[(r + 8) * RSW + kp];
                aF[ks][mf][2] = sA[r * RSW + kp + 4];
                aF[ks][mf][3] = sA[(r + 8) * RSW + kp + 4];
            }
        }
    }

    int it = 0;
    for (int nt = grp; nt < NT2; nt += NGRP2, it++) {
        const unsigned curB = (it & 1) ? bBase1 : bBase0;
        const unsigned nxtB = (it & 1) ? bBase0 : bBase1;

        if (nt + NGRP2 < NT2) load_B(nt + NGRP2, nxtB);
        cp_commit();
        cp_wait<1>();
        __syncthreads();                 // current B resident

        if (tid < BN) {
            int g = nt * BN + tid;
            sBias[tid] = (g < N_ENT) ? out_bias[g] : 0.f;
        }

        // ---- mainloop: full K, no syncs ------------------------------------
        float acc[2][4][4];
        #pragma unroll
        for (int i = 0; i < 2; i++)
            #pragma unroll
            for (int j = 0; j < 4; j++)
                #pragma unroll
                for (int k = 0; k < 4; k++) acc[i][j][k] = 0.f;

        const unsigned* sB = (const unsigned*)(dynraw + (curB - aBase));
        #pragma unroll
        for (int ks = 0; ks < 8; ks++) {
            const int kp = ks * 8 + (lane & 3);
            #pragma unroll
            for (int nf = 0; nf < 4; nf++) {
                int br = wn * 32 + nf * 8 + (lane >> 2);
                unsigned b0 = sB[br * RSW + kp];
                unsigned b1 = sB[br * RSW + kp + 4];
                mma_f16(acc[0][nf], aF[ks][0], b0, b1);
                mma_f16(acc[1][nf], aF[ks][1], b0, b1);
            }
        }
        __syncthreads();                 // sBias visible; mainloop done

        // ---- epilogue: bias, store, streaming (max, sumexp) ----------------
        const float NEG = -1e30f;
        #pragma unroll
        for (int mf = 0; mf < 2; mf++) {
            #pragma unroll
            for (int h = 0; h < 2; h++) {
                const int rl = wm * 32 + mf * 16 + h * 8 + (lane >> 2);
                const size_t grow = (size_t)(m0 + rl) * N_ENT;
                float mx = NEG;
                #pragma unroll
                for (int nf = 0; nf < 4; nf++) {
                    int c = wn * 32 + nf * 8 + ((lane & 3) << 1);
                    int g = nt * BN + c;
                    float v0 = acc[mf][nf][2 * h]     + sBias[c];
                    float v1 = acc[mf][nf][2 * h + 1] + sBias[c + 1];
                    if (g + 1 < N_ENT) {
                        *(float2*)&out[grow + g] = make_float2(v0, v1);
                    } else if (g < N_ENT) {
                        out[grow + g] = v0;
                        v1 = NEG;
                    } else {
                        v0 = NEG; v1 = NEG;
                    }
                    acc[mf][nf][2 * h]     = v0;
                    acc[mf][nf][2 * h + 1] = v1;
                    mx = fmaxf(mx, fmaxf(v0, v1));
                }
                float s = 0.f;
                #pragma unroll
                for (int nf = 0; nf < 4; nf++)
                    s += __expf(acc[mf][nf][2 * h] - mx)
                       + __expf(acc[mf][nf][2 * h + 1] - mx);
                #pragma unroll
                for (int off = 1; off <= 2; off <<= 1) {
                    float om = __shfl_xor_sync(0xffffffffu, mx, off);
                    float os = __shfl_xor_sync(0xffffffffu, s,  off);
                    float nm = fmaxf(mx, om);
                    s = s * __expf(mx - nm) + os * __expf(om - nm);
                    mx = nm;
                }
                if ((lane & 3) == 0) {
                    sRm[rl][wn] = mx;
                    sRs[rl][wn] = s;
                }
            }
        }
        __syncthreads();
        if (tid < 128) {
            float ma = sRm[tid][0], mb = sRm[tid][1];
            float sa = sRs[tid][0], sb = sRs[tid][1];
            float nm = fmaxf(ma, mb);
            float ss = sa * __expf(ma - nm) + sb * __expf(mb - nm);
            g_pms[(m0 + tid) * NTP + nt] = make_float2(nm, ss);
        }
        __syncthreads();                 // protect sRm/sRs reuse
    }
}

// ---------------- K4: per-row logsumexp + picked (4-stream MLP) --------------
__global__ void lse_kernel(const float* __restrict__ out,
                           const int* __restrict__ labels) {
    int w = threadIdx.x >> 5, lane = threadIdx.x & 31;
    int b = blockIdx.x * 8 + w;        // grid 64 x 256 -> 512 rows
    float mx0 = -1e30f, mx1 = -1e30f, mx2 = -1e30f, mx3 = -1e30f;
    float s0 = 0.f, s1 = 0.f, s2 = 0.f, s3 = 0.f;
    for (int t0 = 0; t0 < NT2; t0 += 128) {
        int t = t0 + lane;
        if (t < NT2) {
            float2 p = g_pms[b * NTP + t];
            float nm = fmaxf(mx0, p.x);
            s0 = s0 * __expf(mx0 - nm) + p.y * __expf(p.x - nm); mx0 = nm;
        }
        if (t + 32 < NT2) {
            float2 p = g_pms[b * NTP + t + 32];
            float nm = fmaxf(mx1, p.x);
            s1 = s1 * __expf(mx1 - nm) + p.y * __expf(p.x - nm); mx1 = nm;
        }
        if (t + 64 < NT2) {
            float2 p = g_pms[b * NTP + t + 64];
            float nm = fmaxf(mx2, p.x);
            s2 = s2 * __expf(mx2 - nm) + p.y * __expf(p.x - nm); mx2 = nm;
        }
        if (t + 96 < NT2) {
            float2 p = g_pms[b * NTP + t + 96];
            float nm = fmaxf(mx3, p.x);
            s3 = s3 * __expf(mx3 - nm) + p.y * __expf(p.x - nm); mx3 = nm;
        }
    }
    float nm01 = fmaxf(mx0, mx1);
    float s01  = s0 * __expf(mx0 - nm01) + s1 * __expf(mx1 - nm01);
    float nm23 = fmaxf(mx2, mx3);
    float s23  = s2 * __expf(mx2 - nm23) + s3 * __expf(mx3 - nm23);
    float mx   = fmaxf(nm01, nm23);
    float s    = s01 * __expf(nm01 - mx) + s23 * __expf(nm23 - mx);
    #pragma unroll
    for (int o = 16; o; o >>= 1) {
        float om = __shfl_xor_sync(0xffffffffu, mx, o);
        float os = __shfl_xor_sync(0xffffffffu, s,  o);
        float nm = fmaxf(mx, om);
        s = s * __expf(mx - nm) + os * __expf(om - nm);
        mx = nm;
    }
    if (lane == 0) {
        float logz = mx + logf(s);
        g_lp[b] = logz - out[(size_t)b * N_ENT + labels[b]];
    }
}

// ---------------- K5: mean loss -> tail of d_out ------------------------------
__global__ void loss_kernel(float* __restrict__ out, int out_size) {
    int tid = threadIdx.x;             // 512
    __shared__ float red[BATCH];
    red[tid] = g_lp[tid];
    __syncthreads();
    for (int o = 256; o; o >>= 1) {
        if (tid < o) red[tid] += red[tid + o];
        __syncthreads();
    }
    __shared__ float loss_s;
    if (tid == 0) loss_s = red[0] / (float)BATCH;
    __syncthreads();
    const long base = (long)BATCH * N_ENT;
    for (long i = base + tid; i < (long)out_size; i += 512)
        out[i] = loss_s;
}

// ---------------- launch ------------------------------------------------------
extern "C" void kernel_launch(void* const* d_in, const int* in_sizes, int n_in,
                              void* d_out, int out_size) {
    const float* entity_emb = (const float*)d_in[0];
    const float* W1         = (const float*)d_in[1];
    const float* W2         = (const float*)d_in[2];
    const float* q          = (const float*)d_in[3];
    const float* soft_bias  = (const float*)d_in[4];
    const float* out_bias   = (const float*)d_in[5];
    const int*   seed_sets  = (const int*)d_in[6];   // jax default: int64 -> int32
    const int*   labels     = (const int*)d_in[7];
    float* out = (float*)d_out;

    const int dyn_bytes = ABYTES + 2 * BBYTES;       // 69,632 B
    cudaFuncSetAttribute(gemm_kernel,
                         cudaFuncAttributeMaxDynamicSharedMemorySize, dyn_bytes);

    k1_kernel<<<4089, 256>>>(entity_emb, W1, W2, q, soft_bias);
    uemb_kernel<<<BATCH, dim3(128, 8)>>>(entity_emb, seed_sets);
    gemm_kernel<<<4 * NGRP2, 256, dyn_bytes>>>(out_bias, out);
    lse_kernel<<<64, 256>>>(out, labels);
    loss_kernel<<<1, BATCH>>>(out, out_size);
}